// round 14
// baseline (speedup 1.0000x reference)
#include <cuda_runtime.h>
#include <cuda_bf16.h>
#include <cuda_fp16.h>
#include <math_constants.h>
#include <cstdint>

#define Bn 4
#define Hn 16
#define Sn 2048
#define Dn 128
#define Mn (Bn*Hn*Sn)

// Q: frag-linear hi/mid planes (uint4 per (rowblk16, j, lane)).
__device__ __align__(16) uint4 g_qfh[(size_t)Mn * 16];
__device__ __align__(16) uint4 g_qfm[(size_t)Mn * 16];
// K/V: pre-swizzled per-32-key-tile blocks, 24KB each = 1536 uint4:
// [bh*64 + kt] -> { Kh 8KB | Km 8KB | Vf 8KB }, layout == attn smem stage.
__device__ __align__(16) uint4 g_kv[(size_t)(Bn*Hn*64) * 1536];
// pre-split, pre-swizzled W images: [wsel][2048 uint4 hi | 2048 uint4 mid]
__device__ __align__(16) uint4 g_wimg[3 * 4096];

// ---------------- helpers ----------------
__device__ __forceinline__ uint32_t smem_u32(const void* p) {
    uint32_t a;
    asm("{ .reg .u64 t; cvta.to.shared.u64 t, %1; cvt.u32.u64 %0, t; }" : "=r"(a) : "l"(p));
    return a;
}
__device__ __forceinline__ void ldsm4(uint32_t* r, uint32_t a) {
    asm volatile("ldmatrix.sync.aligned.m8n8.x4.shared.b16 {%0,%1,%2,%3}, [%4];"
        : "=r"(r[0]), "=r"(r[1]), "=r"(r[2]), "=r"(r[3]) : "r"(a));
}
__device__ __forceinline__ void ldsm4t(uint32_t* r, uint32_t a) {
    asm volatile("ldmatrix.sync.aligned.m8n8.x4.trans.shared.b16 {%0,%1,%2,%3}, [%4];"
        : "=r"(r[0]), "=r"(r[1]), "=r"(r[2]), "=r"(r[3]) : "r"(a));
}
__device__ __forceinline__ void mma16816(float* d, const uint32_t* a, uint32_t b0, uint32_t b1) {
    asm volatile("mma.sync.aligned.m16n8k16.row.col.f32.bf16.bf16.f32 "
        "{%0,%1,%2,%3}, {%4,%5,%6,%7}, {%8,%9}, {%0,%1,%2,%3};"
        : "+f"(d[0]), "+f"(d[1]), "+f"(d[2]), "+f"(d[3])
        : "r"(a[0]), "r"(a[1]), "r"(a[2]), "r"(a[3]), "r"(b0), "r"(b1));
}
__device__ __forceinline__ void mma16816h(float* d, const uint32_t* a, uint32_t b0, uint32_t b1) {
    asm volatile("mma.sync.aligned.m16n8k16.row.col.f32.f16.f16.f32 "
        "{%0,%1,%2,%3}, {%4,%5,%6,%7}, {%8,%9}, {%0,%1,%2,%3};"
        : "+f"(d[0]), "+f"(d[1]), "+f"(d[2]), "+f"(d[3])
        : "r"(a[0]), "r"(a[1]), "r"(a[2]), "r"(a[3]), "r"(b0), "r"(b1));
}
__device__ __forceinline__ uint32_t bf2(float hi, float lo) {
    uint32_t r; asm("cvt.rn.bf16x2.f32 %0, %1, %2;" : "=r"(r) : "f"(hi), "f"(lo));
    return r;
}
__device__ __forceinline__ uint32_t pk16(float lo, float hi) {
    uint32_t r; asm("cvt.rn.f16x2.f32 %0, %1, %2;" : "=r"(r) : "f"(hi), "f"(lo));
    return r;
}
__device__ __forceinline__ void mk_pf(uint32_t& h, uint32_t& m, float lo, float hi) {
    h = bf2(hi, lo);
    m = bf2(hi - __uint_as_float(h & 0xffff0000u), lo - __uint_as_float(h << 16));
}
#define CP16(dst, src) \
    asm volatile("cp.async.cg.shared.global [%0], [%1], 16;" :: "r"(dst), "l"(src) : "memory")
#define CP_COMMIT() asm volatile("cp.async.commit_group;" ::: "memory")
#define CP_WAIT4()  asm volatile("cp.async.wait_group 4;" ::: "memory")
#define CP_WAIT0()  asm volatile("cp.async.wait_group 0;" ::: "memory")

#define STG_SZ 24576u          // per-stage: Kh 8K | Km 8K | Vf 8K
#define N_STG 8u               // 8 shared stages = 192KB

// swizzled byte offset inside a 32-key tile plane (256B per key row)
__device__ __forceinline__ uint32_t kvsw(int keyl, int c /*element col*/) {
    return (uint32_t)(keyl * 256 + ((((c >> 3) ^ (keyl & 7))) << 4) + ((2 * c) & 15));
}

// ---------------------------------------------------------------------------
// Kernel 0: pre-split W into swizzled bf16 hi/mid images. grid (3, 8).
// ---------------------------------------------------------------------------
__global__ void __launch_bounds__(256) prep_w(
    const float* __restrict__ Wq, const float* __restrict__ Wk,
    const float* __restrict__ Wv)
{
    const float* Ws[3] = {Wq, Wk, Wv};
    const float* __restrict__ W = Ws[blockIdx.x];
    uint4* img = g_wimg + blockIdx.x * 4096;
    int slot = threadIdx.x + blockIdx.y * 256;   // 2048 slots over 8 blocks
    int e = slot >> 4, q = slot & 15;
    float4 a = *(const float4*)(W + (size_t)e * Dn + q * 8);
    float4 b = *(const float4*)(W + (size_t)e * Dn + q * 8 + 4);
    uint4 H, M;
    mk_pf(((uint32_t*)&H)[0], ((uint32_t*)&M)[0], a.x, a.y);
    mk_pf(((uint32_t*)&H)[1], ((uint32_t*)&M)[1], a.z, a.w);
    mk_pf(((uint32_t*)&H)[2], ((uint32_t*)&M)[2], b.x, b.y);
    mk_pf(((uint32_t*)&H)[3], ((uint32_t*)&M)[3], b.z, b.w);
    int so = e * 16 + (q ^ (e & 7));
    img[so] = H;
    img[2048 + so] = M;
}

// ---------------------------------------------------------------------------
// Kernel 1: QKV projection, bf16x3 mma.sync. 128 threads / 64 rows per CTA,
// single 64KB W buffer + 33KB staging (97KB -> 2 CTAs/SM).
// Q stored frag-linear; K/V written as PRE-SWIZZLED 24KB tile blocks.
// ---------------------------------------------------------------------------
__global__ void __launch_bounds__(128) proj_mma(
    const float* __restrict__ x,
    const float* __restrict__ bq, const float* __restrict__ bk,
    const float* __restrict__ bv)
{
    extern __shared__ char smc[];            // W 64KB | stage 33KB
    const uint32_t sb = smem_u32(smc);
    char* stg = smc + 65536;                 // staging (x f32, then K/V images)
    float* xsf = (float*)stg;                // [64][132] f32

    const int tid = threadIdx.x, lane = tid & 31, w = tid >> 5;
    const int t4 = lane & 3, g = lane >> 2;
    const int l8 = lane & 7, sel = lane >> 3;
    const int m0 = blockIdx.x * 64;
    const int kt0 = (m0 >> 11) * 64 + ((m0 & 2047) >> 5);   // global kv tile idx

    // cp.async W image 0 (4096 uint4, 32/thread)
    #pragma unroll
    for (int t = 0; t < 32; t++) {
        int i = tid + t * 128;
        CP16(sb + (uint32_t)i * 16u, g_wimg + i);
    }
    CP_COMMIT();

    {   // stage x tile [64][128] f32, coalesced float4
        const float4* x4 = (const float4*)(x + (size_t)m0 * Dn);
        #pragma unroll
        for (int t = 0; t < 16; t++) {
            int slot = tid + t * 128;        // 2048 float4 slots
            int row = slot >> 5, q = slot & 31;
            *(float4*)(xsf + row * 132 + q * 4) = x4[(size_t)row * 32 + q];
        }
    }
    __syncthreads();

    // build x fragments (hi+mid) for 8 k16-chunks
    uint32_t xh[8][4], xm[8][4];
    {
        const float* xr0 = xsf + (w * 16 + g) * 132;
        const float* xr1 = xr0 + 8 * 132;
        #pragma unroll
        for (int j = 0; j < 8; j++) {
            float2 v00 = *(const float2*)(xr0 + j*16 + 2*t4);
            float2 v10 = *(const float2*)(xr1 + j*16 + 2*t4);
            float2 v01 = *(const float2*)(xr0 + j*16 + 8 + 2*t4);
            float2 v11 = *(const float2*)(xr1 + j*16 + 8 + 2*t4);
            mk_pf(xh[j][0], xm[j][0], v00.x, v00.y);
            mk_pf(xh[j][1], xm[j][1], v10.x, v10.y);
            mk_pf(xh[j][2], xm[j][2], v01.x, v01.y);
            mk_pf(xh[j][3], xm[j][3], v11.x, v11.y);
        }
    }

    const int row0 = w * 16 + g;             // local key row (0..63)

    for (int wsel = 0; wsel < 3; wsel++) {
        CP_WAIT0();
        __syncthreads();                      // W image visible; prev epilogue done

        float acc[16][4];
        #pragma unroll
        for (int t = 0; t < 16; t++)
            #pragma unroll
            for (int i = 0; i < 4; i++) acc[t][i] = 0.f;

        #pragma unroll
        for (int j = 0; j < 8; j++) {
            #pragma unroll
            for (int np = 0; np < 8; np++) {
                int e  = np * 16 + ((sel >> 1) << 3) + l8;
                int dd = j * 16 + ((sel & 1) << 3);
                uint32_t a = sb + e * 256 + ((((dd >> 3) ^ (e & 7))) << 4);
                uint32_t wh4[4], wm4[4];
                ldsm4(wh4, a);
                ldsm4(wm4, a + 32768);
                mma16816(acc[2*np],   xh[j], wh4[0], wh4[1]);
                mma16816(acc[2*np],   xh[j], wm4[0], wm4[1]);
                mma16816(acc[2*np],   xm[j], wh4[0], wh4[1]);
                mma16816(acc[2*np+1], xh[j], wh4[2], wh4[3]);
                mma16816(acc[2*np+1], xh[j], wm4[2], wm4[3]);
                mma16816(acc[2*np+1], xm[j], wh4[2], wh4[3]);
            }
        }

        __syncthreads();                      // all W reads done
        if (wsel < 2) {                       // refill single W buffer
            #pragma unroll
            for (int t = 0; t < 32; t++) {
                int i = tid + t * 128;
                CP16(sb + (uint32_t)i * 16u, g_wimg + (wsel + 1) * 4096 + i);
            }
            CP_COMMIT();
        }

        if (wsel == 0) {
            // Q epilogue: frag-linear, coalesced STG.128 (matches attn A-frags)
            const int rowblk = (m0 >> 4) + w;
            uint4* dh = g_qfh + (size_t)rowblk * 256 + lane;
            uint4* dm = g_qfm + (size_t)rowblk * 256 + lane;
            #pragma unroll
            for (int j = 0; j < 8; j++) {
                int c = j * 16 + 2 * t4;
                float b0 = __ldg(bq + c),     b1 = __ldg(bq + c + 1);
                float b2 = __ldg(bq + c + 8), b3 = __ldg(bq + c + 9);
                uint4 H, M;
                mk_pf(H.x, M.x, acc[2*j][0] + b0,   acc[2*j][1] + b1);
                mk_pf(H.y, M.y, acc[2*j][2] + b0,   acc[2*j][3] + b1);
                mk_pf(H.z, M.z, acc[2*j+1][0] + b2, acc[2*j+1][1] + b3);
                mk_pf(H.w, M.w, acc[2*j+1][2] + b2, acc[2*j+1][3] + b3);
                dh[j * 32] = H;
                dm[j * 32] = M;
            }
        } else if (wsel == 1) {
            // K epilogue: split + STS into swizzled staging image (hi|mid per tile)
            const int ts0 = (row0 >> 5) * 16384, ts1 = ((row0 + 8) >> 5) * 16384;
            const int k0 = row0 & 31, k1 = (row0 + 8) & 31;
            #pragma unroll
            for (int np = 0; np < 8; np++) {
                #pragma unroll
                for (int hf = 0; hf < 2; hf++) {
                    int c = np * 16 + hf * 8 + 2 * t4;
                    float b0 = __ldg(bk + c), b1 = __ldg(bk + c + 1);
                    const float* av = acc[2*np + hf];
                    uint32_t h, m;
                    mk_pf(h, m, av[0] + b0, av[1] + b1);
                    uint32_t o0 = (uint32_t)ts0 + kvsw(k0, c);
                    *(uint32_t*)(stg + o0) = h;
                    *(uint32_t*)(stg + o0 + 8192) = m;
                    mk_pf(h, m, av[2] + b0, av[3] + b1);
                    uint32_t o1 = (uint32_t)ts1 + kvsw(k1, c);
                    *(uint32_t*)(stg + o1) = h;
                    *(uint32_t*)(stg + o1 + 8192) = m;
                }
            }
            __syncthreads();
            const uint4* st4 = (const uint4*)stg;
            #pragma unroll
            for (int ts = 0; ts < 2; ts++) {
                uint4* dst = g_kv + (size_t)(kt0 + ts) * 1536;
                #pragma unroll
                for (int t = 0; t < 8; t++) {
                    int i = tid + t * 128;   // 1024 uint4 = hi(512) + mid(512)
                    dst[i] = st4[ts * 1024 + i];
                }
            }
        } else {
            // V epilogue: fp16 pairs, swizzled staging, copy to +16KB of blocks
            const int ts0 = (row0 >> 5) * 8192, ts1 = ((row0 + 8) >> 5) * 8192;
            const int k0 = row0 & 31, k1 = (row0 + 8) & 31;
            #pragma unroll
            for (int np = 0; np < 8; np++) {
                #pragma unroll
                for (int hf = 0; hf < 2; hf++) {
                    int c = np * 16 + hf * 8 + 2 * t4;
                    float b0 = __ldg(bv + c), b1 = __ldg(bv + c + 1);
                    const float* av = acc[2*np + hf];
                    *(uint32_t*)(stg + ts0 + kvsw(k0, c)) = pk16(av[0] + b0, av[1] + b1);
                    *(uint32_t*)(stg + ts1 + kvsw(k1, c)) = pk16(av[2] + b0, av[3] + b1);
                }
            }
            __syncthreads();
            const uint4* st4 = (const uint4*)stg;
            #pragma unroll
            for (int ts = 0; ts < 2; ts++) {
                uint4* dst = g_kv + (size_t)(kt0 + ts) * 1536 + 1024;  // +16KB
                #pragma unroll
                for (int t = 0; t < 4; t++) {
                    int i = tid + t * 128;   // 512 uint4 = Vf 8KB
                    dst[i] = st4[ts * 512 + i];
                }
            }
        }
    }
}

// ---------------------------------------------------------------------------
// Kernel 2: flash attention. QK bf16x3, online-max softmax (warp-voted lazy
// O-rescale), PV single-term fp16. ONE SHARED 8-stage cp.async pipeline for
// all 8 warps (halves de-duplicated: half the cp issue + L2 traffic), one
// __syncthreads per tile, 6-tile prefetch distance (wait_group 4 ledger).
// ---------------------------------------------------------------------------
__device__ __forceinline__ void issue_kv32(uint32_t db, const uint4* __restrict__ src,
                                           int tid)
{
    #pragma unroll
    for (int t = 0; t < 6; t++) {
        int i = tid + t * 256;               // 1536 uint4 = 24KB block
        CP16(db + (uint32_t)i * 16u, src + i);
    }
}

__device__ __forceinline__ void qk_plain(float (&dst)[4][4], uint32_t kb,
    const uint32_t (&qh)[8][4], const uint32_t (&qm)[8][4], int sel, int l8)
{
    #pragma unroll
    for (int t = 0; t < 4; t++)
        #pragma unroll
        for (int i = 0; i < 4; i++) dst[t][i] = 0.f;
    #pragma unroll
    for (int j = 0; j < 8; j++) {
        #pragma unroll
        for (int np = 0; np < 2; np++) {
            int key = np * 16 + ((sel >> 1) << 3) + l8;
            int dd  = j * 16 + ((sel & 1) << 3);
            uint32_t a = kb + key * 256 + ((((dd >> 3) ^ (key & 7))) << 4);
            uint32_t kh4[4], km4[4];
            ldsm4(kh4, a);
            ldsm4(km4, a + 8192);
            mma16816(dst[2*np],   qh[j], kh4[0], kh4[1]);
            mma16816(dst[2*np],   qh[j], km4[0], km4[1]);
            mma16816(dst[2*np],   qm[j], kh4[0], kh4[1]);
            mma16816(dst[2*np+1], qh[j], kh4[2], kh4[3]);
            mma16816(dst[2*np+1], qh[j], km4[2], km4[3]);
            mma16816(dst[2*np+1], qm[j], kh4[2], kh4[3]);
        }
    }
}

// QK of NEXT tile into nxt, exp(cur - mn) fused into the mma stream
__device__ __forceinline__ void qknext_exp(float (&cur)[4][4], float (&nxt)[4][4],
    uint32_t kbn, const uint32_t (&qh)[8][4], const uint32_t (&qm)[8][4],
    float mn0, float mn1, float& l0, float& l1, int sel, int l8)
{
    #pragma unroll
    for (int t = 0; t < 4; t++)
        #pragma unroll
        for (int i = 0; i < 4; i++) nxt[t][i] = 0.f;
    #pragma unroll
    for (int j = 0; j < 8; j++) {
        #pragma unroll
        for (int np = 0; np < 2; np++) {
            int key = np * 16 + ((sel >> 1) << 3) + l8;
            int dd  = j * 16 + ((sel & 1) << 3);
            uint32_t a = kbn + key * 256 + ((((dd >> 3) ^ (key & 7))) << 4);
            uint32_t kh4[4], km4[4];
            ldsm4(kh4, a);
            ldsm4(km4, a + 8192);
            mma16816(nxt[2*np],   qh[j], kh4[0], kh4[1]);
            mma16816(nxt[2*np],   qh[j], km4[0], km4[1]);
            mma16816(nxt[2*np],   qm[j], kh4[0], kh4[1]);
            mma16816(nxt[2*np+1], qh[j], kh4[2], kh4[3]);
            mma16816(nxt[2*np+1], qh[j], km4[2], km4[3]);
            mma16816(nxt[2*np+1], qm[j], kh4[2], kh4[3]);
        }
        if ((j & 1) == 0) {
            int t = j >> 1;
            float p0 = __expf(cur[t][0] - mn0), p1 = __expf(cur[t][1] - mn0);
            float p2 = __expf(cur[t][2] - mn1), p3 = __expf(cur[t][3] - mn1);
            cur[t][0] = p0; cur[t][1] = p1; cur[t][2] = p2; cur[t][3] = p3;
            l0 += p0 + p1; l1 += p2 + p3;
        }
    }
}

__device__ __forceinline__ void exp_only(float (&cur)[4][4], float mn0, float mn1,
                                         float& l0, float& l1)
{
    #pragma unroll
    for (int t = 0; t < 4; t++) {
        float p0 = __expf(cur[t][0] - mn0), p1 = __expf(cur[t][1] - mn0);
        float p2 = __expf(cur[t][2] - mn1), p3 = __expf(cur[t][3] - mn1);
        cur[t][0] = p0; cur[t][1] = p1; cur[t][2] = p2; cur[t][3] = p3;
        l0 += p0 + p1; l1 += p2 + p3;
    }
}

__device__ __forceinline__ void pv_tile(float (&cur)[4][4], float (&oacc)[16][4],
                                        uint32_t kb, int sel, int l8)
{
    #pragma unroll
    for (int j = 0; j < 2; j++) {
        uint32_t pf[4];
        pf[0] = pk16(cur[2*j][0],   cur[2*j][1]);
        pf[1] = pk16(cur[2*j][2],   cur[2*j][3]);
        pf[2] = pk16(cur[2*j+1][0], cur[2*j+1][1]);
        pf[3] = pk16(cur[2*j+1][2], cur[2*j+1][3]);
        #pragma unroll
        for (int np = 0; np < 8; np++) {
            int key = j * 16 + ((sel & 1) << 3) + l8;
            int dd  = np * 16 + ((sel >> 1) << 3);
            uint32_t a = kb + 16384u + key * 256 + ((((dd >> 3) ^ (key & 7))) << 4);
            uint32_t vf4[4];
            ldsm4t(vf4, a);
            mma16816h(oacc[2*np],   pf, vf4[0], vf4[1]);
            mma16816h(oacc[2*np+1], pf, vf4[2], vf4[3]);
        }
    }
}

__global__ void __launch_bounds__(256) attn_mma(float* __restrict__ out)
{
    extern __shared__ char smc[];   // 8 shared stages x 24KB = 192KB
    const uint32_t sb = smem_u32(smc);

    const int tid = threadIdx.x, lane = tid & 31, w = tid >> 5;
    const int t4 = lane & 3, g = lane >> 2;
    const int l8 = lane & 7, sel = lane >> 3;
    const int bh = blockIdx.y, q0 = blockIdx.x * 128;
    const int r0 = q0 + w * 16 + g;          // rows r0, r0+8
    const uint4* __restrict__ kvb = g_kv + (size_t)bh * 64 * 1536;

    // prologue: fill 6 of 8 stages (one commit group per tile)
    #pragma unroll
    for (int s = 0; s < 6; s++) {
        issue_kv32(sb + (uint32_t)s * STG_SZ, kvb + s * 1536, tid);
        CP_COMMIT();
    }

    // Q fragments: frag-linear coalesced LDG.128
    uint32_t qh[8][4], qm[8][4];
    {
        const int rowblk = (bh * Sn + q0 + w * 16) >> 4;
        const uint4* ph4 = g_qfh + (size_t)rowblk * 256 + lane;
        const uint4* pm4 = g_qfm + (size_t)rowblk * 256 + lane;
        #pragma unroll
        for (int j = 0; j < 8; j++) {
            uint4 H = ph4[j * 32];
            uint4 M = pm4[j * 32];
            qh[j][0] = H.x; qh[j][1] = H.y; qh[j][2] = H.z; qh[j][3] = H.w;
            qm[j][0] = M.x; qm[j][1] = M.y; qm[j][2] = M.z; qm[j][3] = M.w;
        }
    }

    float oacc[16][4];
    #pragma unroll
    for (int t = 0; t < 16; t++)
        #pragma unroll
        for (int i = 0; i < 4; i++) oacc[t][i] = 0.f;
    float l0 = 0.f, l1 = 0.f;
    float m0r = -CUDART_INF_F, m1r = -CUDART_INF_F;
    float sA[4][4], sB[4][4];

    // prologue QK(0): committed 6 groups, wait_group 4 -> tiles 0,1 resident
    CP_WAIT4();
    __syncthreads();
    qk_plain(sA, sb, qh, qm, sel, l8);

#define SUBTILE(kt, CUR, NXT) do {                                            \
    CP_WAIT4();  /* committed kt+6 groups -> tiles kt, kt+1 resident */       \
    __syncthreads();                                                          \
    if ((kt) + 6 < 64)                                                        \
        issue_kv32(sb + (uint32_t)(((kt) + 6) & 7) * STG_SZ,                  \
                   kvb + ((kt) + 6) * 1536, tid);                             \
    CP_COMMIT();                                                              \
    uint32_t kb_c = sb + (uint32_t)((kt) & 7) * STG_SZ;                       \
    uint32_t kb_n = sb + (uint32_t)(((kt) + 1) & 7) * STG_SZ;                 \
    float mx0 = -CUDART_INF_F, mx1 = -CUDART_INF_F;                           \
    _Pragma("unroll")                                                         \
    for (int t = 0; t < 4; t++) {                                             \
        mx0 = fmaxf(mx0, fmaxf(CUR[t][0], CUR[t][1]));                        \
        mx1 = fmaxf(mx1, fmaxf(CUR[t][2], CUR[t][3]));                        \
    }                                                                         \
    mx0 = fmaxf(mx0, __shfl_xor_sync(0xffffffffu, mx0, 1));                   \
    mx0 = fmaxf(mx0, __shfl_xor_sync(0xffffffffu, mx0, 2));                   \
    mx1 = fmaxf(mx1, __shfl_xor_sync(0xffffffffu, mx1, 1));                   \
    mx1 = fmaxf(mx1, __shfl_xor_sync(0xffffffffu, mx1, 2));                   \
    float mn0 = fmaxf(m0r, mx0), mn1 = fmaxf(m1r, mx1);                       \
    float sc0 = __expf(m0r - mn0), sc1 = __expf(m1r - mn1);                   \
    m0r = mn0; m1r = mn1;                                                     \
    l0 *= sc0; l1 *= sc1;                                                     \
    if (__any_sync(0xffffffffu, (sc0 < 0.99999f) | (sc1 < 0.99999f))) {       \
        _Pragma("unroll")                                                     \
        for (int t = 0; t < 16; t++) {                                        \
            oacc[t][0] *= sc0; oacc[t][1] *= sc0;                             \
            oacc[t][2] *= sc1; oacc[t][3] *= sc1;                             \
        }                                                                     \
    }                                                                         \
    if ((kt) < 63) qknext_exp(CUR, NXT, kb_n, qh, qm, mn0, mn1, l0, l1, sel, l8); \
    else           exp_only(CUR, mn0, mn1, l0, l1);                           \
    pv_tile(CUR, oacc, kb_c, sel, l8);                                        \
} while (0)

    for (int it = 0; it < 32; it++) {
        int kt = 2 * it;
        SUBTILE(kt,     sA, sB);
        SUBTILE(kt + 1, sB, sA);
    }
#undef SUBTILE

    // ---- epilogue ----
    l0 += __shfl_xor_sync(0xffffffffu, l0, 1);
    l0 += __shfl_xor_sync(0xffffffffu, l0, 2);
    l1 += __shfl_xor_sync(0xffffffffu, l1, 1);
    l1 += __shfl_xor_sync(0xffffffffu, l1, 2);
    const float inv0 = 1.f / l0, inv1 = 1.f / l1;

    const int b = bh >> 4, h = bh & 15;
    const size_t ob0 = (((size_t)b * Sn + r0) * Hn + h) * Dn;
    const size_t ob1 = (((size_t)b * Sn + r0 + 8) * Hn + h) * Dn;
    #pragma unroll
    for (int t = 0; t < 16; t++) {
        int d = t * 8 + 2 * t4;
        *(float2*)(out + ob0 + d) = make_float2(oacc[t][0] * inv0, oacc[t][1] * inv0);
        *(float2*)(out + ob1 + d) = make_float2(oacc[t][2] * inv1, oacc[t][3] * inv1);
    }
}

// ---------------------------------------------------------------------------
extern "C" void kernel_launch(void* const* d_in, const int* in_sizes, int n_in,
                              void* d_out, int out_size)
{
    const float* x  = (const float*)d_in[0];
    const float* Wq = (const float*)d_in[1];
    const float* bq = (const float*)d_in[2];
    const float* Wk = (const float*)d_in[3];
    const float* bk = (const float*)d_in[4];
    const float* Wv = (const float*)d_in[5];
    const float* bv = (const float*)d_in[6];

    const int smem_proj = 65536 + 64 * 132 * 4;    // 99328 -> 2 CTAs/SM
    const int smem_attn = (int)(N_STG * STG_SZ);   // 196608

    cudaFuncSetAttribute(proj_mma, cudaFuncAttributeMaxDynamicSharedMemorySize, smem_proj);
    cudaFuncSetAttribute(attn_mma, cudaFuncAttributeMaxDynamicSharedMemorySize, smem_attn);

    prep_w<<<dim3(3, 8), 256>>>(Wq, Wk, Wv);
    proj_mma<<<Mn / 64, 128, smem_proj>>>(x, bq, bk, bv);
    attn_mma<<<dim3(Sn / 128, Bn * Hn), 256, smem_attn>>>((float*)d_out);
}

// round 15
// speedup vs baseline: 1.0432x; 1.0432x over previous
#include <cuda_runtime.h>
#include <cuda_bf16.h>
#include <cuda_fp16.h>
#include <math_constants.h>
#include <cstdint>

#define Bn 4
#define Hn 16
#define Sn 2048
#define Dn 128
#define Mn (Bn*Hn*Sn)

// Q: frag-linear hi/mid planes (uint4 per (rowblk16, j, lane)).
__device__ __align__(16) uint4 g_qfh[(size_t)Mn * 16];
__device__ __align__(16) uint4 g_qfm[(size_t)Mn * 16];
// K/V: pre-swizzled per-32-key-tile blocks, 24KB each = 1536 uint4:
// [bh*64 + kt] -> { Kh 8KB | Km 8KB | Vf 8KB }, layout == attn smem stage.
__device__ __align__(16) uint4 g_kv[(size_t)(Bn*Hn*64) * 1536];
// pre-split, pre-swizzled W images: [wsel][2048 uint4 hi | 2048 uint4 mid]
__device__ __align__(16) uint4 g_wimg[3 * 4096];

// ---------------- helpers ----------------
__device__ __forceinline__ uint32_t smem_u32(const void* p) {
    uint32_t a;
    asm("{ .reg .u64 t; cvta.to.shared.u64 t, %1; cvt.u32.u64 %0, t; }" : "=r"(a) : "l"(p));
    return a;
}
__device__ __forceinline__ void ldsm4(uint32_t* r, uint32_t a) {
    asm volatile("ldmatrix.sync.aligned.m8n8.x4.shared.b16 {%0,%1,%2,%3}, [%4];"
        : "=r"(r[0]), "=r"(r[1]), "=r"(r[2]), "=r"(r[3]) : "r"(a));
}
__device__ __forceinline__ void ldsm4t(uint32_t* r, uint32_t a) {
    asm volatile("ldmatrix.sync.aligned.m8n8.x4.trans.shared.b16 {%0,%1,%2,%3}, [%4];"
        : "=r"(r[0]), "=r"(r[1]), "=r"(r[2]), "=r"(r[3]) : "r"(a));
}
__device__ __forceinline__ void mma16816(float* d, const uint32_t* a, uint32_t b0, uint32_t b1) {
    asm volatile("mma.sync.aligned.m16n8k16.row.col.f32.bf16.bf16.f32 "
        "{%0,%1,%2,%3}, {%4,%5,%6,%7}, {%8,%9}, {%0,%1,%2,%3};"
        : "+f"(d[0]), "+f"(d[1]), "+f"(d[2]), "+f"(d[3])
        : "r"(a[0]), "r"(a[1]), "r"(a[2]), "r"(a[3]), "r"(b0), "r"(b1));
}
__device__ __forceinline__ void mma16816h(float* d, const uint32_t* a, uint32_t b0, uint32_t b1) {
    asm volatile("mma.sync.aligned.m16n8k16.row.col.f32.f16.f16.f32 "
        "{%0,%1,%2,%3}, {%4,%5,%6,%7}, {%8,%9}, {%0,%1,%2,%3};"
        : "+f"(d[0]), "+f"(d[1]), "+f"(d[2]), "+f"(d[3])
        : "r"(a[0]), "r"(a[1]), "r"(a[2]), "r"(a[3]), "r"(b0), "r"(b1));
}
__device__ __forceinline__ uint32_t bf2(float hi, float lo) {
    uint32_t r; asm("cvt.rn.bf16x2.f32 %0, %1, %2;" : "=r"(r) : "f"(hi), "f"(lo));
    return r;
}
__device__ __forceinline__ uint32_t pk16(float lo, float hi) {
    uint32_t r; asm("cvt.rn.f16x2.f32 %0, %1, %2;" : "=r"(r) : "f"(hi), "f"(lo));
    return r;
}
__device__ __forceinline__ void mk_pf(uint32_t& h, uint32_t& m, float lo, float hi) {
    h = bf2(hi, lo);
    m = bf2(hi - __uint_as_float(h & 0xffff0000u), lo - __uint_as_float(h << 16));
}
#define CP16(dst, src) \
    asm volatile("cp.async.cg.shared.global [%0], [%1], 16;" :: "r"(dst), "l"(src) : "memory")
#define CP_COMMIT() asm volatile("cp.async.commit_group;" ::: "memory")
#define CP_WAIT2()  asm volatile("cp.async.wait_group 2;" ::: "memory")
#define CP_WAIT1()  asm volatile("cp.async.wait_group 1;" ::: "memory")
#define CP_WAIT0()  asm volatile("cp.async.wait_group 0;" ::: "memory")
#define NBAR(id)    asm volatile("bar.sync %0, %1;" :: "r"(id), "r"(128) : "memory")

#define STG_SZ 24576u          // per-stage: Kh 8K | Km 8K | Vf 8K
#define HALF_SZ (4u * STG_SZ)  // 4 stages = 98304

// swizzled byte offset inside a 32-key tile plane (256B per key row)
__device__ __forceinline__ uint32_t kvsw(int keyl, int c /*element col*/) {
    return (uint32_t)(keyl * 256 + ((((c >> 3) ^ (keyl & 7))) << 4) + ((2 * c) & 15));
}

// ---------------------------------------------------------------------------
// Kernel 0: pre-split W into swizzled bf16 hi/mid images. grid (3, 8).
// ---------------------------------------------------------------------------
__global__ void __launch_bounds__(256) prep_w(
    const float* __restrict__ Wq, const float* __restrict__ Wk,
    const float* __restrict__ Wv)
{
    const float* Ws[3] = {Wq, Wk, Wv};
    const float* __restrict__ W = Ws[blockIdx.x];
    uint4* img = g_wimg + blockIdx.x * 4096;
    int slot = threadIdx.x + blockIdx.y * 256;   // 2048 slots over 8 blocks
    int e = slot >> 4, q = slot & 15;
    float4 a = *(const float4*)(W + (size_t)e * Dn + q * 8);
    float4 b = *(const float4*)(W + (size_t)e * Dn + q * 8 + 4);
    uint4 H, M;
    mk_pf(((uint32_t*)&H)[0], ((uint32_t*)&M)[0], a.x, a.y);
    mk_pf(((uint32_t*)&H)[1], ((uint32_t*)&M)[1], a.z, a.w);
    mk_pf(((uint32_t*)&H)[2], ((uint32_t*)&M)[2], b.x, b.y);
    mk_pf(((uint32_t*)&H)[3], ((uint32_t*)&M)[3], b.z, b.w);
    int so = e * 16 + (q ^ (e & 7));
    img[so] = H;
    img[2048 + so] = M;
}

// ---------------------------------------------------------------------------
// Kernel 1: QKV projection, bf16x3 mma.sync. 128 threads / 64 rows per CTA.
// W streamed as SIX 32KB e-half chunks through a 2-buffer cp.async pipeline
// (2x32KB + 33KB staging = 97KB -> 2 CTAs/SM); each chunk load hides behind
// the previous chunk's 192 MMAs. Q stored frag-linear; K/V written as
// PRE-SWIZZLED 24KB tile blocks.
// ---------------------------------------------------------------------------
__global__ void __launch_bounds__(128) proj_mma(
    const float* __restrict__ x,
    const float* __restrict__ bq, const float* __restrict__ bk,
    const float* __restrict__ bv)
{
    extern __shared__ char smc[];            // chunk buf0 32KB | buf1 32KB | stage 33KB
    const uint32_t sb = smem_u32(smc);
    char* stg = smc + 65536;                 // staging (x f32, then K/V images)
    float* xsf = (float*)stg;                // [64][132] f32

    const int tid = threadIdx.x, lane = tid & 31, w = tid >> 5;
    const int t4 = lane & 3, g = lane >> 2;
    const int l8 = lane & 7, sel = lane >> 3;
    const int m0 = blockIdx.x * 64;
    const int kt0 = (m0 >> 11) * 64 + ((m0 & 2047) >> 5);   // global kv tile idx

    // prefetch chunk 0 (wsel0, e 0-63): hi 16KB + mid 16KB
    #pragma unroll
    for (int t = 0; t < 8; t++) {
        int i = tid + t * 128;               // 1024 uint4 per plane-half
        CP16(sb + (uint32_t)i * 16u,            g_wimg + i);
        CP16(sb + 16384u + (uint32_t)i * 16u,   g_wimg + 2048 + i);
    }
    CP_COMMIT();

    {   // stage x tile [64][128] f32, coalesced float4
        const float4* x4 = (const float4*)(x + (size_t)m0 * Dn);
        #pragma unroll
        for (int t = 0; t < 16; t++) {
            int slot = tid + t * 128;        // 2048 float4 slots
            int row = slot >> 5, q = slot & 31;
            *(float4*)(xsf + row * 132 + q * 4) = x4[(size_t)row * 32 + q];
        }
    }
    __syncthreads();

    // build x fragments (hi+mid) for 8 k16-chunks
    uint32_t xh[8][4], xm[8][4];
    {
        const float* xr0 = xsf + (w * 16 + g) * 132;
        const float* xr1 = xr0 + 8 * 132;
        #pragma unroll
        for (int j = 0; j < 8; j++) {
            float2 v00 = *(const float2*)(xr0 + j*16 + 2*t4);
            float2 v10 = *(const float2*)(xr1 + j*16 + 2*t4);
            float2 v01 = *(const float2*)(xr0 + j*16 + 8 + 2*t4);
            float2 v11 = *(const float2*)(xr1 + j*16 + 8 + 2*t4);
            mk_pf(xh[j][0], xm[j][0], v00.x, v00.y);
            mk_pf(xh[j][1], xm[j][1], v10.x, v10.y);
            mk_pf(xh[j][2], xm[j][2], v01.x, v01.y);
            mk_pf(xh[j][3], xm[j][3], v11.x, v11.y);
        }
    }

    const int row0 = w * 16 + g;             // local key row (0..63)
    float acc[16][4];

    for (int c = 0; c < 6; c++) {
        const int wsel = c >> 1, chalf = c & 1;

        __syncthreads();                      // WAR: readers of buffer (c+1)&1 done
        if (c + 1 < 6) {                      // prefetch chunk c+1
            const uint4* src = g_wimg + ((c + 1) >> 1) * 4096 + ((c + 1) & 1) * 1024;
            uint32_t db = sb + (uint32_t)((c + 1) & 1) * 32768u;
            #pragma unroll
            for (int t = 0; t < 8; t++) {
                int i = tid + t * 128;
                CP16(db + (uint32_t)i * 16u,          src + i);
                CP16(db + 16384u + (uint32_t)i * 16u, src + 2048 + i);
            }
        }
        CP_COMMIT();
        CP_WAIT1();                           // chunk c landed (c+1 in flight)
        __syncthreads();                      // chunk c visible CTA-wide

        if (chalf == 0) {
            #pragma unroll
            for (int t = 0; t < 16; t++)
                #pragma unroll
                for (int i = 0; i < 4; i++) acc[t][i] = 0.f;
        }

        const uint32_t cb = sb + (uint32_t)(c & 1) * 32768u;
        #pragma unroll
        for (int j = 0; j < 8; j++) {
            #pragma unroll
            for (int npl = 0; npl < 4; npl++) {
                const int np = chalf * 4 + npl;
                int el = npl * 16 + ((sel >> 1) << 3) + l8;   // local e 0..63
                int dd = j * 16 + ((sel & 1) << 3);
                uint32_t a = cb + el * 256 + ((((dd >> 3) ^ (el & 7))) << 4);
                uint32_t wh4[4], wm4[4];
                ldsm4(wh4, a);
                ldsm4(wm4, a + 16384);
                mma16816(acc[2*np],   xh[j], wh4[0], wh4[1]);
                mma16816(acc[2*np],   xh[j], wm4[0], wm4[1]);
                mma16816(acc[2*np],   xm[j], wh4[0], wh4[1]);
                mma16816(acc[2*np+1], xh[j], wh4[2], wh4[3]);
                mma16816(acc[2*np+1], xh[j], wm4[2], wm4[3]);
                mma16816(acc[2*np+1], xm[j], wh4[2], wh4[3]);
            }
        }

        if (chalf != 1) continue;
        // ------------- epilogue for this wsel (acc complete) -------------
        if (wsel == 0) {
            // Q epilogue: frag-linear, coalesced STG.128 (matches attn A-frags)
            const int rowblk = (m0 >> 4) + w;
            uint4* dh = g_qfh + (size_t)rowblk * 256 + lane;
            uint4* dm = g_qfm + (size_t)rowblk * 256 + lane;
            #pragma unroll
            for (int j = 0; j < 8; j++) {
                int cc = j * 16 + 2 * t4;
                float b0 = __ldg(bq + cc),     b1 = __ldg(bq + cc + 1);
                float b2 = __ldg(bq + cc + 8), b3 = __ldg(bq + cc + 9);
                uint4 H, M;
                mk_pf(H.x, M.x, acc[2*j][0] + b0,   acc[2*j][1] + b1);
                mk_pf(H.y, M.y, acc[2*j][2] + b0,   acc[2*j][3] + b1);
                mk_pf(H.z, M.z, acc[2*j+1][0] + b2, acc[2*j+1][1] + b3);
                mk_pf(H.w, M.w, acc[2*j+1][2] + b2, acc[2*j+1][3] + b3);
                dh[j * 32] = H;
                dm[j * 32] = M;
            }
        } else if (wsel == 1) {
            // K epilogue: split + STS into swizzled staging image (hi|mid per tile)
            const int ts0 = (row0 >> 5) * 16384, ts1 = ((row0 + 8) >> 5) * 16384;
            const int k0 = row0 & 31, k1 = (row0 + 8) & 31;
            #pragma unroll
            for (int np = 0; np < 8; np++) {
                #pragma unroll
                for (int hf = 0; hf < 2; hf++) {
                    int cc = np * 16 + hf * 8 + 2 * t4;
                    float b0 = __ldg(bk + cc), b1 = __ldg(bk + cc + 1);
                    const float* av = acc[2*np + hf];
                    uint32_t h, m;
                    mk_pf(h, m, av[0] + b0, av[1] + b1);
                    uint32_t o0 = (uint32_t)ts0 + kvsw(k0, cc);
                    *(uint32_t*)(stg + o0) = h;
                    *(uint32_t*)(stg + o0 + 8192) = m;
                    mk_pf(h, m, av[2] + b0, av[3] + b1);
                    uint32_t o1 = (uint32_t)ts1 + kvsw(k1, cc);
                    *(uint32_t*)(stg + o1) = h;
                    *(uint32_t*)(stg + o1 + 8192) = m;
                }
            }
            __syncthreads();
            const uint4* st4 = (const uint4*)stg;
            #pragma unroll
            for (int ts = 0; ts < 2; ts++) {
                uint4* dst = g_kv + (size_t)(kt0 + ts) * 1536;
                #pragma unroll
                for (int t = 0; t < 8; t++) {
                    int i = tid + t * 128;   // 1024 uint4 = hi(512) + mid(512)
                    dst[i] = st4[ts * 1024 + i];
                }
            }
        } else {
            // V epilogue: fp16 pairs, swizzled staging, copy to +16KB of blocks
            const int ts0 = (row0 >> 5) * 8192, ts1 = ((row0 + 8) >> 5) * 8192;
            const int k0 = row0 & 31, k1 = (row0 + 8) & 31;
            #pragma unroll
            for (int np = 0; np < 8; np++) {
                #pragma unroll
                for (int hf = 0; hf < 2; hf++) {
                    int cc = np * 16 + hf * 8 + 2 * t4;
                    float b0 = __ldg(bv + cc), b1 = __ldg(bv + cc + 1);
                    const float* av = acc[2*np + hf];
                    *(uint32_t*)(stg + ts0 + kvsw(k0, cc)) = pk16(av[0] + b0, av[1] + b1);
                    *(uint32_t*)(stg + ts1 + kvsw(k1, cc)) = pk16(av[2] + b0, av[3] + b1);
                }
            }
            __syncthreads();
            const uint4* st4 = (const uint4*)stg;
            #pragma unroll
            for (int ts = 0; ts < 2; ts++) {
                uint4* dst = g_kv + (size_t)(kt0 + ts) * 1536 + 1024;  // +16KB
                #pragma unroll
                for (int t = 0; t < 4; t++) {
                    int i = tid + t * 128;   // 512 uint4 = Vf 8KB
                    dst[i] = st4[ts * 512 + i];
                }
            }
        }
    }
}

// ---------------------------------------------------------------------------
// Kernel 2: flash attention (R13 verbatim — best known). QK bf16x3, online-max
// softmax (warp-voted lazy O-rescale), PV single-term fp16. 4-stage cp.async
// per half, one named barrier per tile, wait_group 2 ledger.
// ---------------------------------------------------------------------------
__device__ __forceinline__ void issue_kv32(uint32_t db, const uint4* __restrict__ src,
                                           int t128)
{
    #pragma unroll
    for (int t = 0; t < 12; t++) {
        int i = t128 + t * 128;              // 1536 uint4 = 24KB block
        CP16(db + (uint32_t)i * 16u, src + i);
    }
}

__device__ __forceinline__ void qk_plain(float (&dst)[4][4], uint32_t kb,
    const uint32_t (&qh)[8][4], const uint32_t (&qm)[8][4], int sel, int l8)
{
    #pragma unroll
    for (int t = 0; t < 4; t++)
        #pragma unroll
        for (int i = 0; i < 4; i++) dst[t][i] = 0.f;
    #pragma unroll
    for (int j = 0; j < 8; j++) {
        #pragma unroll
        for (int np = 0; np < 2; np++) {
            int key = np * 16 + ((sel >> 1) << 3) + l8;
            int dd  = j * 16 + ((sel & 1) << 3);
            uint32_t a = kb + key * 256 + ((((dd >> 3) ^ (key & 7))) << 4);
            uint32_t kh4[4], km4[4];
            ldsm4(kh4, a);
            ldsm4(km4, a + 8192);
            mma16816(dst[2*np],   qh[j], kh4[0], kh4[1]);
            mma16816(dst[2*np],   qh[j], km4[0], km4[1]);
            mma16816(dst[2*np],   qm[j], kh4[0], kh4[1]);
            mma16816(dst[2*np+1], qh[j], kh4[2], kh4[3]);
            mma16816(dst[2*np+1], qh[j], km4[2], km4[3]);
            mma16816(dst[2*np+1], qm[j], kh4[2], kh4[3]);
        }
    }
}

__device__ __forceinline__ void qknext_exp(float (&cur)[4][4], float (&nxt)[4][4],
    uint32_t kbn, const uint32_t (&qh)[8][4], const uint32_t (&qm)[8][4],
    float mn0, float mn1, float& l0, float& l1, int sel, int l8)
{
    #pragma unroll
    for (int t = 0; t < 4; t++)
        #pragma unroll
        for (int i = 0; i < 4; i++) nxt[t][i] = 0.f;
    #pragma unroll
    for (int j = 0; j < 8; j++) {
        #pragma unroll
        for (int np = 0; np < 2; np++) {
            int key = np * 16 + ((sel >> 1) << 3) + l8;
            int dd  = j * 16 + ((sel & 1) << 3);
            uint32_t a = kbn + key * 256 + ((((dd >> 3) ^ (key & 7))) << 4);
            uint32_t kh4[4], km4[4];
            ldsm4(kh4, a);
            ldsm4(km4, a + 8192);
            mma16816(nxt[2*np],   qh[j], kh4[0], kh4[1]);
            mma16816(nxt[2*np],   qh[j], km4[0], km4[1]);
            mma16816(nxt[2*np],   qm[j], kh4[0], kh4[1]);
            mma16816(nxt[2*np+1], qh[j], kh4[2], kh4[3]);
            mma16816(nxt[2*np+1], qh[j], km4[2], km4[3]);
            mma16816(nxt[2*np+1], qm[j], kh4[2], kh4[3]);
        }
        if ((j & 1) == 0) {
            int t = j >> 1;
            float p0 = __expf(cur[t][0] - mn0), p1 = __expf(cur[t][1] - mn0);
            float p2 = __expf(cur[t][2] - mn1), p3 = __expf(cur[t][3] - mn1);
            cur[t][0] = p0; cur[t][1] = p1; cur[t][2] = p2; cur[t][3] = p3;
            l0 += p0 + p1; l1 += p2 + p3;
        }
    }
}

__device__ __forceinline__ void exp_only(float (&cur)[4][4], float mn0, float mn1,
                                         float& l0, float& l1)
{
    #pragma unroll
    for (int t = 0; t < 4; t++) {
        float p0 = __expf(cur[t][0] - mn0), p1 = __expf(cur[t][1] - mn0);
        float p2 = __expf(cur[t][2] - mn1), p3 = __expf(cur[t][3] - mn1);
        cur[t][0] = p0; cur[t][1] = p1; cur[t][2] = p2; cur[t][3] = p3;
        l0 += p0 + p1; l1 += p2 + p3;
    }
}

__device__ __forceinline__ void pv_tile(float (&cur)[4][4], float (&oacc)[16][4],
                                        uint32_t kb, int sel, int l8)
{
    #pragma unroll
    for (int j = 0; j < 2; j++) {
        uint32_t pf[4];
        pf[0] = pk16(cur[2*j][0],   cur[2*j][1]);
        pf[1] = pk16(cur[2*j][2],   cur[2*j][3]);
        pf[2] = pk16(cur[2*j+1][0], cur[2*j+1][1]);
        pf[3] = pk16(cur[2*j+1][2], cur[2*j+1][3]);
        #pragma unroll
        for (int np = 0; np < 8; np++) {
            int key = j * 16 + ((sel & 1) << 3) + l8;
            int dd  = np * 16 + ((sel >> 1) << 3);
            uint32_t a = kb + 16384u + key * 256 + ((((dd >> 3) ^ (key & 7))) << 4);
            uint32_t vf4[4];
            ldsm4t(vf4, a);
            mma16816h(oacc[2*np],   pf, vf4[0], vf4[1]);
            mma16816h(oacc[2*np+1], pf, vf4[2], vf4[3]);
        }
    }
}

__global__ void __launch_bounds__(256) attn_mma(float* __restrict__ out)
{
    extern __shared__ char smc[];   // 2 halves x 4 stages x 24KB = 192KB
    const uint32_t sb = smem_u32(smc);

    const int tid = threadIdx.x, lane = tid & 31, w = tid >> 5;
    const int t4 = lane & 3, g = lane >> 2;
    const int l8 = lane & 7, sel = lane >> 3;
    const int half = w >> 2, t128 = tid & 127;
    const int bh = blockIdx.y, q0 = blockIdx.x * 128;
    const int r0 = q0 + w * 16 + g;          // rows r0, r0+8
    const uint32_t hb = sb + (uint32_t)half * HALF_SZ;
    const int barid = half + 1;
    const uint4* __restrict__ kvb = g_kv + (size_t)bh * 64 * 1536;

    issue_kv32(hb,               kvb,            t128); CP_COMMIT();
    issue_kv32(hb + STG_SZ,      kvb + 1536,     t128); CP_COMMIT();
    issue_kv32(hb + 2u * STG_SZ, kvb + 2 * 1536, t128); CP_COMMIT();
    issue_kv32(hb + 3u * STG_SZ, kvb + 3 * 1536, t128); CP_COMMIT();

    // Q fragments: frag-linear coalesced LDG.128
    uint32_t qh[8][4], qm[8][4];
    {
        const int rowblk = (bh * Sn + q0 + w * 16) >> 4;
        const uint4* ph4 = g_qfh + (size_t)rowblk * 256 + lane;
        const uint4* pm4 = g_qfm + (size_t)rowblk * 256 + lane;
        #pragma unroll
        for (int j = 0; j < 8; j++) {
            uint4 H = ph4[j * 32];
            uint4 M = pm4[j * 32];
            qh[j][0] = H.x; qh[j][1] = H.y; qh[j][2] = H.z; qh[j][3] = H.w;
            qm[j][0] = M.x; qm[j][1] = M.y; qm[j][2] = M.z; qm[j][3] = M.w;
        }
    }

    float oacc[16][4];
    #pragma unroll
    for (int t = 0; t < 16; t++)
        #pragma unroll
        for (int i = 0; i < 4; i++) oacc[t][i] = 0.f;
    float l0 = 0.f, l1 = 0.f;
    float m0r = -CUDART_INF_F, m1r = -CUDART_INF_F;
    float sA[4][4], sB[4][4];

    // prologue: QK(0) — WAIT2 guarantees tiles 0 and 1 resident
    CP_WAIT2();
    NBAR(barid);
    qk_plain(sA, hb, qh, qm, sel, l8);

#define SUBTILE(kt, CUR, NXT) do {                                            \
    CP_WAIT2();  /* ledger: guarantees groups for tiles kt and kt+1 */        \
    NBAR(barid);                                                              \
    if ((kt) >= 1 && (kt) + 3 < 64)                                           \
        issue_kv32(hb + (uint32_t)(((kt) + 3) & 3) * STG_SZ,                  \
                   kvb + ((kt) + 3) * 1536, t128);                            \
    CP_COMMIT();                                                              \
    uint32_t kb_c = hb + (uint32_t)((kt) & 3) * STG_SZ;                       \
    uint32_t kb_n = hb + (uint32_t)(((kt) + 1) & 3) * STG_SZ;                 \
    float mx0 = -CUDART_INF_F, mx1 = -CUDART_INF_F;                           \
    _Pragma("unroll")                                                         \
    for (int t = 0; t < 4; t++) {                                             \
        mx0 = fmaxf(mx0, fmaxf(CUR[t][0], CUR[t][1]));                        \
        mx1 = fmaxf(mx1, fmaxf(CUR[t][2], CUR[t][3]));                        \
    }                                                                         \
    mx0 = fmaxf(mx0, __shfl_xor_sync(0xffffffffu, mx0, 1));                   \
    mx0 = fmaxf(mx0, __shfl_xor_sync(0xffffffffu, mx0, 2));                   \
    mx1 = fmaxf(mx1, __shfl_xor_sync(0xffffffffu, mx1, 1));                   \
    mx1 = fmaxf(mx1, __shfl_xor_sync(0xffffffffu, mx1, 2));                   \
    float mn0 = fmaxf(m0r, mx0), mn1 = fmaxf(m1r, mx1);                       \
    float sc0 = __expf(m0r - mn0), sc1 = __expf(m1r - mn1);                   \
    m0r = mn0; m1r = mn1;                                                     \
    l0 *= sc0; l1 *= sc1;                                                     \
    if (__any_sync(0xffffffffu, (sc0 < 0.99999f) | (sc1 < 0.99999f))) {       \
        _Pragma("unroll")                                                     \
        for (int t = 0; t < 16; t++) {                                        \
            oacc[t][0] *= sc0; oacc[t][1] *= sc0;                             \
            oacc[t][2] *= sc1; oacc[t][3] *= sc1;                             \
        }                                                                     \
    }                                                                         \
    if ((kt) < 63) qknext_exp(CUR, NXT, kb_n, qh, qm, mn0, mn1, l0, l1, sel, l8); \
    else           exp_only(CUR, mn0, mn1, l0, l1);                           \
    pv_tile(CUR, oacc, kb_c, sel, l8);                                        \
} while (0)

    for (int it = 0; it < 32; it++) {
        int kt = 2 * it;
        SUBTILE(kt,     sA, sB);
        SUBTILE(kt + 1, sB, sA);
    }
#undef SUBTILE

    // ---- epilogue ----
    l0 += __shfl_xor_sync(0xffffffffu, l0, 1);
    l0 += __shfl_xor_sync(0xffffffffu, l0, 2);
    l1 += __shfl_xor_sync(0xffffffffu, l1, 1);
    l1 += __shfl_xor_sync(0xffffffffu, l1, 2);
    const float inv0 = 1.f / l0, inv1 = 1.f / l1;

    const int b = bh >> 4, h = bh & 15;
    const size_t ob0 = (((size_t)b * Sn + r0) * Hn + h) * Dn;
    const size_t ob1 = (((size_t)b * Sn + r0 + 8) * Hn + h) * Dn;
    #pragma unroll
    for (int t = 0; t < 16; t++) {
        int d = t * 8 + 2 * t4;
        *(float2*)(out + ob0 + d) = make_float2(oacc[t][0] * inv0, oacc[t][1] * inv0);
        *(float2*)(out + ob1 + d) = make_float2(oacc[t][2] * inv1, oacc[t][3] * inv1);
    }
}

// ---------------------------------------------------------------------------
extern "C" void kernel_launch(void* const* d_in, const int* in_sizes, int n_in,
                              void* d_out, int out_size)
{
    const float* x  = (const float*)d_in[0];
    const float* Wq = (const float*)d_in[1];
    const float* bq = (const float*)d_in[2];
    const float* Wk = (const float*)d_in[3];
    const float* bk = (const float*)d_in[4];
    const float* Wv = (const float*)d_in[5];
    const float* bv = (const float*)d_in[6];

    const int smem_proj = 65536 + 64 * 132 * 4;    // 99328 -> 2 CTAs/SM
    const int smem_attn = 2 * (int)HALF_SZ;        // 196608

    cudaFuncSetAttribute(proj_mma, cudaFuncAttributeMaxDynamicSharedMemorySize, smem_proj);
    cudaFuncSetAttribute(attn_mma, cudaFuncAttributeMaxDynamicSharedMemorySize, smem_attn);

    prep_w<<<dim3(3, 8), 256>>>(Wq, Wk, Wv);
    proj_mma<<<Mn / 64, 128, smem_proj>>>(x, bq, bk, bv);
    attn_mma<<<dim3(Sn / 128, Bn * Hn), 256, smem_attn>>>((float*)d_out);
}

// round 16
// speedup vs baseline: 1.0892x; 1.0441x over previous
#include <cuda_runtime.h>
#include <cuda_bf16.h>
#include <cuda_fp16.h>
#include <math_constants.h>
#include <cstdint>

#define Bn 4
#define Hn 16
#define Sn 2048
#define Dn 128
#define Mn (Bn*Hn*Sn)

// Q: frag-linear hi/mid planes (uint4 per (rowblk16, j, lane)).
__device__ __align__(16) uint4 g_qfh[(size_t)Mn * 16];
__device__ __align__(16) uint4 g_qfm[(size_t)Mn * 16];
// K/V: pre-swizzled per-32-key-tile blocks, 24KB each = 1536 uint4:
// [bh*64 + kt] -> { Kh 8KB | Km 8KB | Vf 8KB }, layout == attn smem stage.
__device__ __align__(16) uint4 g_kv[(size_t)(Bn*Hn*64) * 1536];
// pre-split, pre-swizzled W images: [wsel][2048 uint4 hi | 2048 uint4 mid]
__device__ __align__(16) uint4 g_wimg[3 * 4096];

// ---------------- helpers ----------------
__device__ __forceinline__ uint32_t smem_u32(const void* p) {
    uint32_t a;
    asm("{ .reg .u64 t; cvta.to.shared.u64 t, %1; cvt.u32.u64 %0, t; }" : "=r"(a) : "l"(p));
    return a;
}
__device__ __forceinline__ void ldsm4(uint32_t* r, uint32_t a) {
    asm volatile("ldmatrix.sync.aligned.m8n8.x4.shared.b16 {%0,%1,%2,%3}, [%4];"
        : "=r"(r[0]), "=r"(r[1]), "=r"(r[2]), "=r"(r[3]) : "r"(a));
}
__device__ __forceinline__ void ldsm4t(uint32_t* r, uint32_t a) {
    asm volatile("ldmatrix.sync.aligned.m8n8.x4.trans.shared.b16 {%0,%1,%2,%3}, [%4];"
        : "=r"(r[0]), "=r"(r[1]), "=r"(r[2]), "=r"(r[3]) : "r"(a));
}
__device__ __forceinline__ void mma16816(float* d, const uint32_t* a, uint32_t b0, uint32_t b1) {
    asm volatile("mma.sync.aligned.m16n8k16.row.col.f32.bf16.bf16.f32 "
        "{%0,%1,%2,%3}, {%4,%5,%6,%7}, {%8,%9}, {%0,%1,%2,%3};"
        : "+f"(d[0]), "+f"(d[1]), "+f"(d[2]), "+f"(d[3])
        : "r"(a[0]), "r"(a[1]), "r"(a[2]), "r"(a[3]), "r"(b0), "r"(b1));
}
__device__ __forceinline__ void mma16816h(float* d, const uint32_t* a, uint32_t b0, uint32_t b1) {
    asm volatile("mma.sync.aligned.m16n8k16.row.col.f32.f16.f16.f32 "
        "{%0,%1,%2,%3}, {%4,%5,%6,%7}, {%8,%9}, {%0,%1,%2,%3};"
        : "+f"(d[0]), "+f"(d[1]), "+f"(d[2]), "+f"(d[3])
        : "r"(a[0]), "r"(a[1]), "r"(a[2]), "r"(a[3]), "r"(b0), "r"(b1));
}
__device__ __forceinline__ uint32_t bf2(float hi, float lo) {
    uint32_t r; asm("cvt.rn.bf16x2.f32 %0, %1, %2;" : "=r"(r) : "f"(hi), "f"(lo));
    return r;
}
__device__ __forceinline__ uint32_t pk16(float lo, float hi) {
    uint32_t r; asm("cvt.rn.f16x2.f32 %0, %1, %2;" : "=r"(r) : "f"(hi), "f"(lo));
    return r;
}
__device__ __forceinline__ void mk_pf(uint32_t& h, uint32_t& m, float lo, float hi) {
    h = bf2(hi, lo);
    m = bf2(hi - __uint_as_float(h & 0xffff0000u), lo - __uint_as_float(h << 16));
}
#define CP16(dst, src) \
    asm volatile("cp.async.cg.shared.global [%0], [%1], 16;" :: "r"(dst), "l"(src) : "memory")
#define CP_COMMIT() asm volatile("cp.async.commit_group;" ::: "memory")
#define CP_WAIT2()  asm volatile("cp.async.wait_group 2;" ::: "memory")
#define CP_WAIT1()  asm volatile("cp.async.wait_group 1;" ::: "memory")
#define CP_WAIT0()  asm volatile("cp.async.wait_group 0;" ::: "memory")
#define NBAR(id)    asm volatile("bar.sync %0, %1;" :: "r"(id), "r"(128) : "memory")

#define STG_SZ 24576u          // per-stage: Kh 8K | Km 8K | Vf 8K
#define HALF_SZ (4u * STG_SZ)  // 4 stages = 98304

// swizzled byte offset inside a 32-key tile plane (256B per key row)
__device__ __forceinline__ uint32_t kvsw(int keyl, int c /*element col*/) {
    return (uint32_t)(keyl * 256 + ((((c >> 3) ^ (keyl & 7))) << 4) + ((2 * c) & 15));
}

// ---------------------------------------------------------------------------
// Kernel 0: pre-split W into swizzled bf16 hi/mid images. grid (3, 8).
// ---------------------------------------------------------------------------
__global__ void __launch_bounds__(256) prep_w(
    const float* __restrict__ Wq, const float* __restrict__ Wk,
    const float* __restrict__ Wv)
{
    const float* Ws[3] = {Wq, Wk, Wv};
    const float* __restrict__ W = Ws[blockIdx.x];
    uint4* img = g_wimg + blockIdx.x * 4096;
    int slot = threadIdx.x + blockIdx.y * 256;   // 2048 slots over 8 blocks
    int e = slot >> 4, q = slot & 15;
    float4 a = *(const float4*)(W + (size_t)e * Dn + q * 8);
    float4 b = *(const float4*)(W + (size_t)e * Dn + q * 8 + 4);
    uint4 H, M;
    mk_pf(((uint32_t*)&H)[0], ((uint32_t*)&M)[0], a.x, a.y);
    mk_pf(((uint32_t*)&H)[1], ((uint32_t*)&M)[1], a.z, a.w);
    mk_pf(((uint32_t*)&H)[2], ((uint32_t*)&M)[2], b.x, b.y);
    mk_pf(((uint32_t*)&H)[3], ((uint32_t*)&M)[3], b.z, b.w);
    int so = e * 16 + (q ^ (e & 7));
    img[so] = H;
    img[2048 + so] = M;
}

// ---------------------------------------------------------------------------
// Kernel 1: QKV projection, bf16x3 mma.sync. 128 threads / 64 rows per CTA,
// single 64KB W buffer + 33KB staging (97KB -> 2 CTAs/SM).
// Q stored frag-linear; K/V written as PRE-SWIZZLED 24KB tile blocks.
// ---------------------------------------------------------------------------
__global__ void __launch_bounds__(128) proj_mma(
    const float* __restrict__ x,
    const float* __restrict__ bq, const float* __restrict__ bk,
    const float* __restrict__ bv)
{
    extern __shared__ char smc[];            // W 64KB | stage 33KB
    const uint32_t sb = smem_u32(smc);
    char* stg = smc + 65536;                 // staging (x f32, then K/V images)
    float* xsf = (float*)stg;                // [64][132] f32

    const int tid = threadIdx.x, lane = tid & 31, w = tid >> 5;
    const int t4 = lane & 3, g = lane >> 2;
    const int l8 = lane & 7, sel = lane >> 3;
    const int m0 = blockIdx.x * 64;
    const int kt0 = (m0 >> 11) * 64 + ((m0 & 2047) >> 5);   // global kv tile idx

    // cp.async W image 0 (4096 uint4, 32/thread)
    #pragma unroll
    for (int t = 0; t < 32; t++) {
        int i = tid + t * 128;
        CP16(sb + (uint32_t)i * 16u, g_wimg + i);
    }
    CP_COMMIT();

    {   // stage x tile [64][128] f32, coalesced float4
        const float4* x4 = (const float4*)(x + (size_t)m0 * Dn);
        #pragma unroll
        for (int t = 0; t < 16; t++) {
            int slot = tid + t * 128;        // 2048 float4 slots
            int row = slot >> 5, q = slot & 31;
            *(float4*)(xsf + row * 132 + q * 4) = x4[(size_t)row * 32 + q];
        }
    }
    __syncthreads();

    // build x fragments (hi+mid) for 8 k16-chunks
    uint32_t xh[8][4], xm[8][4];
    {
        const float* xr0 = xsf + (w * 16 + g) * 132;
        const float* xr1 = xr0 + 8 * 132;
        #pragma unroll
        for (int j = 0; j < 8; j++) {
            float2 v00 = *(const float2*)(xr0 + j*16 + 2*t4);
            float2 v10 = *(const float2*)(xr1 + j*16 + 2*t4);
            float2 v01 = *(const float2*)(xr0 + j*16 + 8 + 2*t4);
            float2 v11 = *(const float2*)(xr1 + j*16 + 8 + 2*t4);
            mk_pf(xh[j][0], xm[j][0], v00.x, v00.y);
            mk_pf(xh[j][1], xm[j][1], v10.x, v10.y);
            mk_pf(xh[j][2], xm[j][2], v01.x, v01.y);
            mk_pf(xh[j][3], xm[j][3], v11.x, v11.y);
        }
    }

    const int row0 = w * 16 + g;             // local key row (0..63)

    for (int wsel = 0; wsel < 3; wsel++) {
        CP_WAIT0();
        __syncthreads();                      // W image visible; prev epilogue done

        float acc[16][4];
        #pragma unroll
        for (int t = 0; t < 16; t++)
            #pragma unroll
            for (int i = 0; i < 4; i++) acc[t][i] = 0.f;

        #pragma unroll
        for (int j = 0; j < 8; j++) {
            #pragma unroll
            for (int np = 0; np < 8; np++) {
                int e  = np * 16 + ((sel >> 1) << 3) + l8;
                int dd = j * 16 + ((sel & 1) << 3);
                uint32_t a = sb + e * 256 + ((((dd >> 3) ^ (e & 7))) << 4);
                uint32_t wh4[4], wm4[4];
                ldsm4(wh4, a);
                ldsm4(wm4, a + 32768);
                mma16816(acc[2*np],   xh[j], wh4[0], wh4[1]);
                mma16816(acc[2*np],   xh[j], wm4[0], wm4[1]);
                mma16816(acc[2*np],   xm[j], wh4[0], wh4[1]);
                mma16816(acc[2*np+1], xh[j], wh4[2], wh4[3]);
                mma16816(acc[2*np+1], xh[j], wm4[2], wm4[3]);
                mma16816(acc[2*np+1], xm[j], wh4[2], wh4[3]);
            }
        }

        __syncthreads();                      // all W reads done
        if (wsel < 2) {                       // refill single W buffer
            #pragma unroll
            for (int t = 0; t < 32; t++) {
                int i = tid + t * 128;
                CP16(sb + (uint32_t)i * 16u, g_wimg + (wsel + 1) * 4096 + i);
            }
            CP_COMMIT();
        }

        if (wsel == 0) {
            // Q epilogue: frag-linear, coalesced STG.128 (matches attn A-frags)
            const int rowblk = (m0 >> 4) + w;
            uint4* dh = g_qfh + (size_t)rowblk * 256 + lane;
            uint4* dm = g_qfm + (size_t)rowblk * 256 + lane;
            #pragma unroll
            for (int j = 0; j < 8; j++) {
                int c = j * 16 + 2 * t4;
                float b0 = __ldg(bq + c),     b1 = __ldg(bq + c + 1);
                float b2 = __ldg(bq + c + 8), b3 = __ldg(bq + c + 9);
                uint4 H, M;
                mk_pf(H.x, M.x, acc[2*j][0] + b0,   acc[2*j][1] + b1);
                mk_pf(H.y, M.y, acc[2*j][2] + b0,   acc[2*j][3] + b1);
                mk_pf(H.z, M.z, acc[2*j+1][0] + b2, acc[2*j+1][1] + b3);
                mk_pf(H.w, M.w, acc[2*j+1][2] + b2, acc[2*j+1][3] + b3);
                dh[j * 32] = H;
                dm[j * 32] = M;
            }
        } else if (wsel == 1) {
            // K epilogue: split + STS into swizzled staging image (hi|mid per tile)
            const int ts0 = (row0 >> 5) * 16384, ts1 = ((row0 + 8) >> 5) * 16384;
            const int k0 = row0 & 31, k1 = (row0 + 8) & 31;
            #pragma unroll
            for (int np = 0; np < 8; np++) {
                #pragma unroll
                for (int hf = 0; hf < 2; hf++) {
                    int c = np * 16 + hf * 8 + 2 * t4;
                    float b0 = __ldg(bk + c), b1 = __ldg(bk + c + 1);
                    const float* av = acc[2*np + hf];
                    uint32_t h, m;
                    mk_pf(h, m, av[0] + b0, av[1] + b1);
                    uint32_t o0 = (uint32_t)ts0 + kvsw(k0, c);
                    *(uint32_t*)(stg + o0) = h;
                    *(uint32_t*)(stg + o0 + 8192) = m;
                    mk_pf(h, m, av[2] + b0, av[3] + b1);
                    uint32_t o1 = (uint32_t)ts1 + kvsw(k1, c);
                    *(uint32_t*)(stg + o1) = h;
                    *(uint32_t*)(stg + o1 + 8192) = m;
                }
            }
            __syncthreads();
            const uint4* st4 = (const uint4*)stg;
            #pragma unroll
            for (int ts = 0; ts < 2; ts++) {
                uint4* dst = g_kv + (size_t)(kt0 + ts) * 1536;
                #pragma unroll
                for (int t = 0; t < 8; t++) {
                    int i = tid + t * 128;   // 1024 uint4 = hi(512) + mid(512)
                    dst[i] = st4[ts * 1024 + i];
                }
            }
        } else {
            // V epilogue: fp16 pairs, swizzled staging, copy to +16KB of blocks
            const int ts0 = (row0 >> 5) * 8192, ts1 = ((row0 + 8) >> 5) * 8192;
            const int k0 = row0 & 31, k1 = (row0 + 8) & 31;
            #pragma unroll
            for (int np = 0; np < 8; np++) {
                #pragma unroll
                for (int hf = 0; hf < 2; hf++) {
                    int c = np * 16 + hf * 8 + 2 * t4;
                    float b0 = __ldg(bv + c), b1 = __ldg(bv + c + 1);
                    const float* av = acc[2*np + hf];
                    *(uint32_t*)(stg + ts0 + kvsw(k0, c)) = pk16(av[0] + b0, av[1] + b1);
                    *(uint32_t*)(stg + ts1 + kvsw(k1, c)) = pk16(av[2] + b0, av[3] + b1);
                }
            }
            __syncthreads();
            const uint4* st4 = (const uint4*)stg;
            #pragma unroll
            for (int ts = 0; ts < 2; ts++) {
                uint4* dst = g_kv + (size_t)(kt0 + ts) * 1536 + 1024;  // +16KB
                #pragma unroll
                for (int t = 0; t < 4; t++) {
                    int i = tid + t * 128;   // 512 uint4 = Vf 8KB
                    dst[i] = st4[ts * 512 + i];
                }
            }
        }
    }
}

// ---------------------------------------------------------------------------
// Kernel 2: flash attention. QK bf16x3, online-max softmax (warp-voted lazy
// O-rescale), PV single-term fp16. 4-stage cp.async per half, one named
// barrier per tile; wait_group 2 ledger. K/V loads are pure linear copies of
// pre-swizzled blocks.
// ---------------------------------------------------------------------------
__device__ __forceinline__ void issue_kv32(uint32_t db, const uint4* __restrict__ src,
                                           int t128)
{
    #pragma unroll
    for (int t = 0; t < 12; t++) {
        int i = t128 + t * 128;              // 1536 uint4 = 24KB block
        CP16(db + (uint32_t)i * 16u, src + i);
    }
}

__device__ __forceinline__ void qk_plain(float (&dst)[4][4], uint32_t kb,
    const uint32_t (&qh)[8][4], const uint32_t (&qm)[8][4], int sel, int l8)
{
    #pragma unroll
    for (int t = 0; t < 4; t++)
        #pragma unroll
        for (int i = 0; i < 4; i++) dst[t][i] = 0.f;
    #pragma unroll
    for (int j = 0; j < 8; j++) {
        #pragma unroll
        for (int np = 0; np < 2; np++) {
            int key = np * 16 + ((sel >> 1) << 3) + l8;
            int dd  = j * 16 + ((sel & 1) << 3);
            uint32_t a = kb + key * 256 + ((((dd >> 3) ^ (key & 7))) << 4);
            uint32_t kh4[4], km4[4];
            ldsm4(kh4, a);
            ldsm4(km4, a + 8192);
            mma16816(dst[2*np],   qh[j], kh4[0], kh4[1]);
            mma16816(dst[2*np],   qh[j], km4[0], km4[1]);
            mma16816(dst[2*np],   qm[j], kh4[0], kh4[1]);
            mma16816(dst[2*np+1], qh[j], kh4[2], kh4[3]);
            mma16816(dst[2*np+1], qh[j], km4[2], km4[3]);
            mma16816(dst[2*np+1], qm[j], kh4[2], kh4[3]);
        }
    }
}

// QK of NEXT tile into nxt, exp(cur - mn) fused into the mma stream
__device__ __forceinline__ void qknext_exp(float (&cur)[4][4], float (&nxt)[4][4],
    uint32_t kbn, const uint32_t (&qh)[8][4], const uint32_t (&qm)[8][4],
    float mn0, float mn1, float& l0, float& l1, int sel, int l8)
{
    #pragma unroll
    for (int t = 0; t < 4; t++)
        #pragma unroll
        for (int i = 0; i < 4; i++) nxt[t][i] = 0.f;
    #pragma unroll
    for (int j = 0; j < 8; j++) {
        #pragma unroll
        for (int np = 0; np < 2; np++) {
            int key = np * 16 + ((sel >> 1) << 3) + l8;
            int dd  = j * 16 + ((sel & 1) << 3);
            uint32_t a = kbn + key * 256 + ((((dd >> 3) ^ (key & 7))) << 4);
            uint32_t kh4[4], km4[4];
            ldsm4(kh4, a);
            ldsm4(km4, a + 8192);
            mma16816(nxt[2*np],   qh[j], kh4[0], kh4[1]);
            mma16816(nxt[2*np],   qh[j], km4[0], km4[1]);
            mma16816(nxt[2*np],   qm[j], kh4[0], kh4[1]);
            mma16816(nxt[2*np+1], qh[j], kh4[2], kh4[3]);
            mma16816(nxt[2*np+1], qh[j], km4[2], km4[3]);
            mma16816(nxt[2*np+1], qm[j], kh4[2], kh4[3]);
        }
        if ((j & 1) == 0) {
            int t = j >> 1;
            float p0 = __expf(cur[t][0] - mn0), p1 = __expf(cur[t][1] - mn0);
            float p2 = __expf(cur[t][2] - mn1), p3 = __expf(cur[t][3] - mn1);
            cur[t][0] = p0; cur[t][1] = p1; cur[t][2] = p2; cur[t][3] = p3;
            l0 += p0 + p1; l1 += p2 + p3;
        }
    }
}

__device__ __forceinline__ void exp_only(float (&cur)[4][4], float mn0, float mn1,
                                         float& l0, float& l1)
{
    #pragma unroll
    for (int t = 0; t < 4; t++) {
        float p0 = __expf(cur[t][0] - mn0), p1 = __expf(cur[t][1] - mn0);
        float p2 = __expf(cur[t][2] - mn1), p3 = __expf(cur[t][3] - mn1);
        cur[t][0] = p0; cur[t][1] = p1; cur[t][2] = p2; cur[t][3] = p3;
        l0 += p0 + p1; l1 += p2 + p3;
    }
}

__device__ __forceinline__ void pv_tile(float (&cur)[4][4], float (&oacc)[16][4],
                                        uint32_t kb, int sel, int l8)
{
    #pragma unroll
    for (int j = 0; j < 2; j++) {
        uint32_t pf[4];
        pf[0] = pk16(cur[2*j][0],   cur[2*j][1]);
        pf[1] = pk16(cur[2*j][2],   cur[2*j][3]);
        pf[2] = pk16(cur[2*j+1][0], cur[2*j+1][1]);
        pf[3] = pk16(cur[2*j+1][2], cur[2*j+1][3]);
        #pragma unroll
        for (int np = 0; np < 8; np++) {
            int key = j * 16 + ((sel & 1) << 3) + l8;
            int dd  = np * 16 + ((sel >> 1) << 3);
            uint32_t a = kb + 16384u + key * 256 + ((((dd >> 3) ^ (key & 7))) << 4);
            uint32_t vf4[4];
            ldsm4t(vf4, a);
            mma16816h(oacc[2*np],   pf, vf4[0], vf4[1]);
            mma16816h(oacc[2*np+1], pf, vf4[2], vf4[3]);
        }
    }
}

__global__ void __launch_bounds__(256) attn_mma(float* __restrict__ out)
{
    extern __shared__ char smc[];   // 2 halves x 4 stages x 24KB = 192KB
    const uint32_t sb = smem_u32(smc);

    const int tid = threadIdx.x, lane = tid & 31, w = tid >> 5;
    const int t4 = lane & 3, g = lane >> 2;
    const int l8 = lane & 7, sel = lane >> 3;
    const int half = w >> 2, t128 = tid & 127;
    const int bh = blockIdx.y, q0 = blockIdx.x * 128;
    const int r0 = q0 + w * 16 + g;          // rows r0, r0+8
    const uint32_t hb = sb + (uint32_t)half * HALF_SZ;
    const int barid = half + 1;
    const uint4* __restrict__ kvb = g_kv + (size_t)bh * 64 * 1536;

    issue_kv32(hb,               kvb,            t128); CP_COMMIT();
    issue_kv32(hb + STG_SZ,      kvb + 1536,     t128); CP_COMMIT();
    issue_kv32(hb + 2u * STG_SZ, kvb + 2 * 1536, t128); CP_COMMIT();
    issue_kv32(hb + 3u * STG_SZ, kvb + 3 * 1536, t128); CP_COMMIT();

    // Q fragments: frag-linear coalesced LDG.128
    uint32_t qh[8][4], qm[8][4];
    {
        const int rowblk = (bh * Sn + q0 + w * 16) >> 4;
        const uint4* ph4 = g_qfh + (size_t)rowblk * 256 + lane;
        const uint4* pm4 = g_qfm + (size_t)rowblk * 256 + lane;
        #pragma unroll
        for (int j = 0; j < 8; j++) {
            uint4 H = ph4[j * 32];
            uint4 M = pm4[j * 32];
            qh[j][0] = H.x; qh[j][1] = H.y; qh[j][2] = H.z; qh[j][3] = H.w;
            qm[j][0] = M.x; qm[j][1] = M.y; qm[j][2] = M.z; qm[j][3] = M.w;
        }
    }

    float oacc[16][4];
    #pragma unroll
    for (int t = 0; t < 16; t++)
        #pragma unroll
        for (int i = 0; i < 4; i++) oacc[t][i] = 0.f;
    float l0 = 0.f, l1 = 0.f;
    float m0r = -CUDART_INF_F, m1r = -CUDART_INF_F;
    float sA[4][4], sB[4][4];

    // prologue: QK(0) — WAIT2 guarantees tiles 0 and 1 resident
    CP_WAIT2();
    NBAR(barid);
    qk_plain(sA, hb, qh, qm, sel, l8);

#define SUBTILE(kt, CUR, NXT) do {                                            \
    CP_WAIT2();  /* ledger: guarantees groups for tiles kt and kt+1 */        \
    NBAR(barid);                                                              \
    if ((kt) >= 1 && (kt) + 3 < 64)                                           \
        issue_kv32(hb + (uint32_t)(((kt) + 3) & 3) * STG_SZ,                  \
                   kvb + ((kt) + 3) * 1536, t128);                            \
    CP_COMMIT();                                                              \
    uint32_t kb_c = hb + (uint32_t)((kt) & 3) * STG_SZ;                       \
    uint32_t kb_n = hb + (uint32_t)(((kt) + 1) & 3) * STG_SZ;                 \
    float mx0 = -CUDART_INF_F, mx1 = -CUDART_INF_F;                           \
    _Pragma("unroll")                                                         \
    for (int t = 0; t < 4; t++) {                                             \
        mx0 = fmaxf(mx0, fmaxf(CUR[t][0], CUR[t][1]));                        \
        mx1 = fmaxf(mx1, fmaxf(CUR[t][2], CUR[t][3]));                        \
    }                                                                         \
    mx0 = fmaxf(mx0, __shfl_xor_sync(0xffffffffu, mx0, 1));                   \
    mx0 = fmaxf(mx0, __shfl_xor_sync(0xffffffffu, mx0, 2));                   \
    mx1 = fmaxf(mx1, __shfl_xor_sync(0xffffffffu, mx1, 1));                   \
    mx1 = fmaxf(mx1, __shfl_xor_sync(0xffffffffu, mx1, 2));                   \
    float mn0 = fmaxf(m0r, mx0), mn1 = fmaxf(m1r, mx1);                       \
    float sc0 = __expf(m0r - mn0), sc1 = __expf(m1r - mn1);                   \
    m0r = mn0; m1r = mn1;                                                     \
    l0 *= sc0; l1 *= sc1;                                                     \
    if (__any_sync(0xffffffffu, (sc0 < 0.99999f) | (sc1 < 0.99999f))) {       \
        _Pragma("unroll")                                                     \
        for (int t = 0; t < 16; t++) {                                        \
            oacc[t][0] *= sc0; oacc[t][1] *= sc0;                             \
            oacc[t][2] *= sc1; oacc[t][3] *= sc1;                             \
        }                                                                     \
    }                                                                         \
    if ((kt) < 63) qknext_exp(CUR, NXT, kb_n, qh, qm, mn0, mn1, l0, l1, sel, l8); \
    else           exp_only(CUR, mn0, mn1, l0, l1);                           \
    pv_tile(CUR, oacc, kb_c, sel, l8);                                        \
} while (0)

    for (int it = 0; it < 32; it++) {
        int kt = 2 * it;
        SUBTILE(kt,     sA, sB);
        SUBTILE(kt + 1, sB, sA);
    }
#undef SUBTILE

    // ---- epilogue ----
    l0 += __shfl_xor_sync(0xffffffffu, l0, 1);
    l0 += __shfl_xor_sync(0xffffffffu, l0, 2);
    l1 += __shfl_xor_sync(0xffffffffu, l1, 1);
    l1 += __shfl_xor_sync(0xffffffffu, l1, 2);
    const float inv0 = 1.f / l0, inv1 = 1.f / l1;

    const int b = bh >> 4, h = bh & 15;
    const size_t ob0 = (((size_t)b * Sn + r0) * Hn + h) * Dn;
    const size_t ob1 = (((size_t)b * Sn + r0 + 8) * Hn + h) * Dn;
    #pragma unroll
    for (int t = 0; t < 16; t++) {
        int d = t * 8 + 2 * t4;
        *(float2*)(out + ob0 + d) = make_float2(oacc[t][0] * inv0, oacc[t][1] * inv0);
        *(float2*)(out + ob1 + d) = make_float2(oacc[t][2] * inv1, oacc[t][3] * inv1);
    }
}

// ---------------------------------------------------------------------------
extern "C" void kernel_launch(void* const* d_in, const int* in_sizes, int n_in,
                              void* d_out, int out_size)
{
    const float* x  = (const float*)d_in[0];
    const float* Wq = (const float*)d_in[1];
    const float* bq = (const float*)d_in[2];
    const float* Wk = (const float*)d_in[3];
    const float* bk = (const float*)d_in[4];
    const float* Wv = (const float*)d_in[5];
    const float* bv = (const float*)d_in[6];

    const int smem_proj = 65536 + 64 * 132 * 4;    // 99328 -> 2 CTAs/SM
    const int smem_attn = 2 * (int)HALF_SZ;        // 196608

    cudaFuncSetAttribute(proj_mma, cudaFuncAttributeMaxDynamicSharedMemorySize, smem_proj);
    cudaFuncSetAttribute(attn_mma, cudaFuncAttributeMaxDynamicSharedMemorySize, smem_attn);

    prep_w<<<dim3(3, 8), 256>>>(Wq, Wk, Wv);
    proj_mma<<<Mn / 64, 128, smem_proj>>>(x, bq, bk, bv);
    attn_mma<<<dim3(Sn / 128, Bn * Hn), 256, smem_attn>>>((float*)d_out);
}

// round 17
// speedup vs baseline: 1.0897x; 1.0004x over previous
#include <cuda_runtime.h>
#include <cuda_bf16.h>
#include <cuda_fp16.h>
#include <math_constants.h>
#include <cstdint>

#define Bn 4
#define Hn 16
#define Sn 2048
#define Dn 128
#define Mn (Bn*Hn*Sn)

// Q: frag-linear hi/mid planes (uint4 per (rowblk16, j, lane)).
__device__ __align__(16) uint4 g_qfh[(size_t)Mn * 16];
__device__ __align__(16) uint4 g_qfm[(size_t)Mn * 16];
// K/V: pre-swizzled per-32-key-tile blocks, 24KB each = 1536 uint4:
// [bh*64 + kt] -> { Kh 8KB | Km 8KB | Vf 8KB }, layout == attn smem stage.
__device__ __align__(16) uint4 g_kv[(size_t)(Bn*Hn*64) * 1536];
// pre-split, pre-swizzled W images: [wsel][2048 uint4 hi | 2048 uint4 mid]
__device__ __align__(16) uint4 g_wimg[3 * 4096];

// ---------------- helpers ----------------
__device__ __forceinline__ uint32_t smem_u32(const void* p) {
    uint32_t a;
    asm("{ .reg .u64 t; cvta.to.shared.u64 t, %1; cvt.u32.u64 %0, t; }" : "=r"(a) : "l"(p));
    return a;
}
__device__ __forceinline__ void ldsm4(uint32_t* r, uint32_t a) {
    asm volatile("ldmatrix.sync.aligned.m8n8.x4.shared.b16 {%0,%1,%2,%3}, [%4];"
        : "=r"(r[0]), "=r"(r[1]), "=r"(r[2]), "=r"(r[3]) : "r"(a));
}
__device__ __forceinline__ void ldsm4t(uint32_t* r, uint32_t a) {
    asm volatile("ldmatrix.sync.aligned.m8n8.x4.trans.shared.b16 {%0,%1,%2,%3}, [%4];"
        : "=r"(r[0]), "=r"(r[1]), "=r"(r[2]), "=r"(r[3]) : "r"(a));
}
__device__ __forceinline__ void mma16816(float* d, const uint32_t* a, uint32_t b0, uint32_t b1) {
    asm volatile("mma.sync.aligned.m16n8k16.row.col.f32.bf16.bf16.f32 "
        "{%0,%1,%2,%3}, {%4,%5,%6,%7}, {%8,%9}, {%0,%1,%2,%3};"
        : "+f"(d[0]), "+f"(d[1]), "+f"(d[2]), "+f"(d[3])
        : "r"(a[0]), "r"(a[1]), "r"(a[2]), "r"(a[3]), "r"(b0), "r"(b1));
}
__device__ __forceinline__ void mma16816h(float* d, const uint32_t* a, uint32_t b0, uint32_t b1) {
    asm volatile("mma.sync.aligned.m16n8k16.row.col.f32.f16.f16.f32 "
        "{%0,%1,%2,%3}, {%4,%5,%6,%7}, {%8,%9}, {%0,%1,%2,%3};"
        : "+f"(d[0]), "+f"(d[1]), "+f"(d[2]), "+f"(d[3])
        : "r"(a[0]), "r"(a[1]), "r"(a[2]), "r"(a[3]), "r"(b0), "r"(b1));
}
__device__ __forceinline__ uint32_t bf2(float hi, float lo) {
    uint32_t r; asm("cvt.rn.bf16x2.f32 %0, %1, %2;" : "=r"(r) : "f"(hi), "f"(lo));
    return r;
}
__device__ __forceinline__ uint32_t pk16(float lo, float hi) {
    uint32_t r; asm("cvt.rn.f16x2.f32 %0, %1, %2;" : "=r"(r) : "f"(hi), "f"(lo));
    return r;
}
__device__ __forceinline__ void mk_pf(uint32_t& h, uint32_t& m, float lo, float hi) {
    h = bf2(hi, lo);
    m = bf2(hi - __uint_as_float(h & 0xffff0000u), lo - __uint_as_float(h << 16));
}
#define CP16(dst, src) \
    asm volatile("cp.async.cg.shared.global [%0], [%1], 16;" :: "r"(dst), "l"(src) : "memory")
#define CP_COMMIT() asm volatile("cp.async.commit_group;" ::: "memory")
#define CP_WAIT2()  asm volatile("cp.async.wait_group 2;" ::: "memory")
#define CP_WAIT1()  asm volatile("cp.async.wait_group 1;" ::: "memory")
#define CP_WAIT0()  asm volatile("cp.async.wait_group 0;" ::: "memory")
#define NBAR(id)    asm volatile("bar.sync %0, %1;" :: "r"(id), "r"(128) : "memory")

#define STG_SZ 24576u          // per-stage: Kh 8K | Km 8K | Vf 8K
#define HALF_SZ (4u * STG_SZ)  // 4 stages = 98304

// swizzled byte offset inside a 32-key tile plane (256B per key row)
__device__ __forceinline__ uint32_t kvsw(int keyl, int c /*element col*/) {
    return (uint32_t)(keyl * 256 + ((((c >> 3) ^ (keyl & 7))) << 4) + ((2 * c) & 15));
}

// ---------------------------------------------------------------------------
// Kernel 0: pre-split W into swizzled bf16 hi/mid images. grid (3, 16) x 128
// (one slot per thread; wider grid for lower latency).
// ---------------------------------------------------------------------------
__global__ void __launch_bounds__(128) prep_w(
    const float* __restrict__ Wq, const float* __restrict__ Wk,
    const float* __restrict__ Wv)
{
    const float* Ws[3] = {Wq, Wk, Wv};
    const float* __restrict__ W = Ws[blockIdx.x];
    uint4* img = g_wimg + blockIdx.x * 4096;
    int slot = threadIdx.x + blockIdx.y * 128;   // 2048 slots over 16 blocks
    int e = slot >> 4, q = slot & 15;
    float4 a = *(const float4*)(W + (size_t)e * Dn + q * 8);
    float4 b = *(const float4*)(W + (size_t)e * Dn + q * 8 + 4);
    uint4 H, M;
    mk_pf(((uint32_t*)&H)[0], ((uint32_t*)&M)[0], a.x, a.y);
    mk_pf(((uint32_t*)&H)[1], ((uint32_t*)&M)[1], a.z, a.w);
    mk_pf(((uint32_t*)&H)[2], ((uint32_t*)&M)[2], b.x, b.y);
    mk_pf(((uint32_t*)&H)[3], ((uint32_t*)&M)[3], b.z, b.w);
    int so = e * 16 + (q ^ (e & 7));
    img[so] = H;
    img[2048 + so] = M;
}

// ---------------------------------------------------------------------------
// Kernel 1: QKV projection, bf16x3 mma.sync. 128 threads / 64 rows per CTA,
// single 64KB W buffer + 33KB staging (97KB -> 2 CTAs/SM).
// Q stored frag-linear; K/V written as PRE-SWIZZLED 24KB tile blocks.
// ---------------------------------------------------------------------------
__global__ void __launch_bounds__(128) proj_mma(
    const float* __restrict__ x,
    const float* __restrict__ bq, const float* __restrict__ bk,
    const float* __restrict__ bv)
{
    extern __shared__ char smc[];            // W 64KB | stage 33KB
    const uint32_t sb = smem_u32(smc);
    char* stg = smc + 65536;                 // staging (x f32, then K/V images)
    float* xsf = (float*)stg;                // [64][132] f32

    const int tid = threadIdx.x, lane = tid & 31, w = tid >> 5;
    const int t4 = lane & 3, g = lane >> 2;
    const int l8 = lane & 7, sel = lane >> 3;
    const int m0 = blockIdx.x * 64;
    const int kt0 = (m0 >> 11) * 64 + ((m0 & 2047) >> 5);   // global kv tile idx

    // cp.async W image 0 (4096 uint4, 32/thread)
    #pragma unroll
    for (int t = 0; t < 32; t++) {
        int i = tid + t * 128;
        CP16(sb + (uint32_t)i * 16u, g_wimg + i);
    }
    CP_COMMIT();

    {   // stage x tile [64][128] f32, coalesced float4
        const float4* x4 = (const float4*)(x + (size_t)m0 * Dn);
        #pragma unroll
        for (int t = 0; t < 16; t++) {
            int slot = tid + t * 128;        // 2048 float4 slots
            int row = slot >> 5, q = slot & 31;
            *(float4*)(xsf + row * 132 + q * 4) = x4[(size_t)row * 32 + q];
        }
    }
    __syncthreads();

    // build x fragments (hi+mid) for 8 k16-chunks
    uint32_t xh[8][4], xm[8][4];
    {
        const float* xr0 = xsf + (w * 16 + g) * 132;
        const float* xr1 = xr0 + 8 * 132;
        #pragma unroll
        for (int j = 0; j < 8; j++) {
            float2 v00 = *(const float2*)(xr0 + j*16 + 2*t4);
            float2 v10 = *(const float2*)(xr1 + j*16 + 2*t4);
            float2 v01 = *(const float2*)(xr0 + j*16 + 8 + 2*t4);
            float2 v11 = *(const float2*)(xr1 + j*16 + 8 + 2*t4);
            mk_pf(xh[j][0], xm[j][0], v00.x, v00.y);
            mk_pf(xh[j][1], xm[j][1], v10.x, v10.y);
            mk_pf(xh[j][2], xm[j][2], v01.x, v01.y);
            mk_pf(xh[j][3], xm[j][3], v11.x, v11.y);
        }
    }

    const int row0 = w * 16 + g;             // local key row (0..63)

    for (int wsel = 0; wsel < 3; wsel++) {
        CP_WAIT0();
        __syncthreads();                      // W image visible; prev epilogue done

        float acc[16][4];
        #pragma unroll
        for (int t = 0; t < 16; t++)
            #pragma unroll
            for (int i = 0; i < 4; i++) acc[t][i] = 0.f;

        #pragma unroll
        for (int j = 0; j < 8; j++) {
            #pragma unroll
            for (int np = 0; np < 8; np++) {
                int e  = np * 16 + ((sel >> 1) << 3) + l8;
                int dd = j * 16 + ((sel & 1) << 3);
                uint32_t a = sb + e * 256 + ((((dd >> 3) ^ (e & 7))) << 4);
                uint32_t wh4[4], wm4[4];
                ldsm4(wh4, a);
                ldsm4(wm4, a + 32768);
                mma16816(acc[2*np],   xh[j], wh4[0], wh4[1]);
                mma16816(acc[2*np],   xh[j], wm4[0], wm4[1]);
                mma16816(acc[2*np],   xm[j], wh4[0], wh4[1]);
                mma16816(acc[2*np+1], xh[j], wh4[2], wh4[3]);
                mma16816(acc[2*np+1], xh[j], wm4[2], wm4[3]);
                mma16816(acc[2*np+1], xm[j], wh4[2], wh4[3]);
            }
        }

        __syncthreads();                      // all W reads done
        if (wsel < 2) {                       // refill single W buffer
            #pragma unroll
            for (int t = 0; t < 32; t++) {
                int i = tid + t * 128;
                CP16(sb + (uint32_t)i * 16u, g_wimg + (wsel + 1) * 4096 + i);
            }
            CP_COMMIT();
        }

        if (wsel == 0) {
            // Q epilogue: frag-linear, coalesced STG.128 (matches attn A-frags)
            const int rowblk = (m0 >> 4) + w;
            uint4* dh = g_qfh + (size_t)rowblk * 256 + lane;
            uint4* dm = g_qfm + (size_t)rowblk * 256 + lane;
            #pragma unroll
            for (int j = 0; j < 8; j++) {
                int c = j * 16 + 2 * t4;
                float b0 = __ldg(bq + c),     b1 = __ldg(bq + c + 1);
                float b2 = __ldg(bq + c + 8), b3 = __ldg(bq + c + 9);
                uint4 H, M;
                mk_pf(H.x, M.x, acc[2*j][0] + b0,   acc[2*j][1] + b1);
                mk_pf(H.y, M.y, acc[2*j][2] + b0,   acc[2*j][3] + b1);
                mk_pf(H.z, M.z, acc[2*j+1][0] + b2, acc[2*j+1][1] + b3);
                mk_pf(H.w, M.w, acc[2*j+1][2] + b2, acc[2*j+1][3] + b3);
                dh[j * 32] = H;
                dm[j * 32] = M;
            }
        } else if (wsel == 1) {
            // K epilogue: split + STS into swizzled staging image (hi|mid per tile)
            const int ts0 = (row0 >> 5) * 16384, ts1 = ((row0 + 8) >> 5) * 16384;
            const int k0 = row0 & 31, k1 = (row0 + 8) & 31;
            #pragma unroll
            for (int np = 0; np < 8; np++) {
                #pragma unroll
                for (int hf = 0; hf < 2; hf++) {
                    int c = np * 16 + hf * 8 + 2 * t4;
                    float b0 = __ldg(bk + c), b1 = __ldg(bk + c + 1);
                    const float* av = acc[2*np + hf];
                    uint32_t h, m;
                    mk_pf(h, m, av[0] + b0, av[1] + b1);
                    uint32_t o0 = (uint32_t)ts0 + kvsw(k0, c);
                    *(uint32_t*)(stg + o0) = h;
                    *(uint32_t*)(stg + o0 + 8192) = m;
                    mk_pf(h, m, av[2] + b0, av[3] + b1);
                    uint32_t o1 = (uint32_t)ts1 + kvsw(k1, c);
                    *(uint32_t*)(stg + o1) = h;
                    *(uint32_t*)(stg + o1 + 8192) = m;
                }
            }
            __syncthreads();
            const uint4* st4 = (const uint4*)stg;
            #pragma unroll
            for (int ts = 0; ts < 2; ts++) {
                uint4* dst = g_kv + (size_t)(kt0 + ts) * 1536;
                #pragma unroll
                for (int t = 0; t < 8; t++) {
                    int i = tid + t * 128;   // 1024 uint4 = hi(512) + mid(512)
                    dst[i] = st4[ts * 1024 + i];
                }
            }
        } else {
            // V epilogue: fp16 pairs, swizzled staging, copy to +16KB of blocks
            const int ts0 = (row0 >> 5) * 8192, ts1 = ((row0 + 8) >> 5) * 8192;
            const int k0 = row0 & 31, k1 = (row0 + 8) & 31;
            #pragma unroll
            for (int np = 0; np < 8; np++) {
                #pragma unroll
                for (int hf = 0; hf < 2; hf++) {
                    int c = np * 16 + hf * 8 + 2 * t4;
                    float b0 = __ldg(bv + c), b1 = __ldg(bv + c + 1);
                    const float* av = acc[2*np + hf];
                    *(uint32_t*)(stg + ts0 + kvsw(k0, c)) = pk16(av[0] + b0, av[1] + b1);
                    *(uint32_t*)(stg + ts1 + kvsw(k1, c)) = pk16(av[2] + b0, av[3] + b1);
                }
            }
            __syncthreads();
            const uint4* st4 = (const uint4*)stg;
            #pragma unroll
            for (int ts = 0; ts < 2; ts++) {
                uint4* dst = g_kv + (size_t)(kt0 + ts) * 1536 + 1024;  // +16KB
                #pragma unroll
                for (int t = 0; t < 4; t++) {
                    int i = tid + t * 128;   // 512 uint4 = Vf 8KB
                    dst[i] = st4[ts * 512 + i];
                }
            }
        }
    }
}

// ---------------------------------------------------------------------------
// Kernel 2: flash attention. QK bf16x3, online-max softmax (warp-voted lazy
// O-rescale), PV single-term fp16. 4-stage cp.async per half, one named
// barrier per tile; wait_group 2 ledger. K/V loads are pure linear copies of
// pre-swizzled blocks.
// ---------------------------------------------------------------------------
__device__ __forceinline__ void issue_kv32(uint32_t db, const uint4* __restrict__ src,
                                           int t128)
{
    #pragma unroll
    for (int t = 0; t < 12; t++) {
        int i = t128 + t * 128;              // 1536 uint4 = 24KB block
        CP16(db + (uint32_t)i * 16u, src + i);
    }
}

__device__ __forceinline__ void qk_plain(float (&dst)[4][4], uint32_t kb,
    const uint32_t (&qh)[8][4], const uint32_t (&qm)[8][4], int sel, int l8)
{
    #pragma unroll
    for (int t = 0; t < 4; t++)
        #pragma unroll
        for (int i = 0; i < 4; i++) dst[t][i] = 0.f;
    #pragma unroll
    for (int j = 0; j < 8; j++) {
        #pragma unroll
        for (int np = 0; np < 2; np++) {
            int key = np * 16 + ((sel >> 1) << 3) + l8;
            int dd  = j * 16 + ((sel & 1) << 3);
            uint32_t a = kb + key * 256 + ((((dd >> 3) ^ (key & 7))) << 4);
            uint32_t kh4[4], km4[4];
            ldsm4(kh4, a);
            ldsm4(km4, a + 8192);
            mma16816(dst[2*np],   qh[j], kh4[0], kh4[1]);
            mma16816(dst[2*np],   qh[j], km4[0], km4[1]);
            mma16816(dst[2*np],   qm[j], kh4[0], kh4[1]);
            mma16816(dst[2*np+1], qh[j], kh4[2], kh4[3]);
            mma16816(dst[2*np+1], qh[j], km4[2], km4[3]);
            mma16816(dst[2*np+1], qm[j], kh4[2], kh4[3]);
        }
    }
}

// QK of NEXT tile into nxt, exp(cur - mn) fused into the mma stream
__device__ __forceinline__ void qknext_exp(float (&cur)[4][4], float (&nxt)[4][4],
    uint32_t kbn, const uint32_t (&qh)[8][4], const uint32_t (&qm)[8][4],
    float mn0, float mn1, float& l0, float& l1, int sel, int l8)
{
    #pragma unroll
    for (int t = 0; t < 4; t++)
        #pragma unroll
        for (int i = 0; i < 4; i++) nxt[t][i] = 0.f;
    #pragma unroll
    for (int j = 0; j < 8; j++) {
        #pragma unroll
        for (int np = 0; np < 2; np++) {
            int key = np * 16 + ((sel >> 1) << 3) + l8;
            int dd  = j * 16 + ((sel & 1) << 3);
            uint32_t a = kbn + key * 256 + ((((dd >> 3) ^ (key & 7))) << 4);
            uint32_t kh4[4], km4[4];
            ldsm4(kh4, a);
            ldsm4(km4, a + 8192);
            mma16816(nxt[2*np],   qh[j], kh4[0], kh4[1]);
            mma16816(nxt[2*np],   qh[j], km4[0], km4[1]);
            mma16816(nxt[2*np],   qm[j], kh4[0], kh4[1]);
            mma16816(nxt[2*np+1], qh[j], kh4[2], kh4[3]);
            mma16816(nxt[2*np+1], qh[j], km4[2], km4[3]);
            mma16816(nxt[2*np+1], qm[j], kh4[2], kh4[3]);
        }
        if ((j & 1) == 0) {
            int t = j >> 1;
            float p0 = __expf(cur[t][0] - mn0), p1 = __expf(cur[t][1] - mn0);
            float p2 = __expf(cur[t][2] - mn1), p3 = __expf(cur[t][3] - mn1);
            cur[t][0] = p0; cur[t][1] = p1; cur[t][2] = p2; cur[t][3] = p3;
            l0 += p0 + p1; l1 += p2 + p3;
        }
    }
}

__device__ __forceinline__ void exp_only(float (&cur)[4][4], float mn0, float mn1,
                                         float& l0, float& l1)
{
    #pragma unroll
    for (int t = 0; t < 4; t++) {
        float p0 = __expf(cur[t][0] - mn0), p1 = __expf(cur[t][1] - mn0);
        float p2 = __expf(cur[t][2] - mn1), p3 = __expf(cur[t][3] - mn1);
        cur[t][0] = p0; cur[t][1] = p1; cur[t][2] = p2; cur[t][3] = p3;
        l0 += p0 + p1; l1 += p2 + p3;
    }
}

__device__ __forceinline__ void pv_tile(float (&cur)[4][4], float (&oacc)[16][4],
                                        uint32_t kb, int sel, int l8)
{
    #pragma unroll
    for (int j = 0; j < 2; j++) {
        uint32_t pf[4];
        pf[0] = pk16(cur[2*j][0],   cur[2*j][1]);
        pf[1] = pk16(cur[2*j][2],   cur[2*j][3]);
        pf[2] = pk16(cur[2*j+1][0], cur[2*j+1][1]);
        pf[3] = pk16(cur[2*j+1][2], cur[2*j+1][3]);
        #pragma unroll
        for (int np = 0; np < 8; np++) {
            int key = j * 16 + ((sel & 1) << 3) + l8;
            int dd  = np * 16 + ((sel >> 1) << 3);
            uint32_t a = kb + 16384u + key * 256 + ((((dd >> 3) ^ (key & 7))) << 4);
            uint32_t vf4[4];
            ldsm4t(vf4, a);
            mma16816h(oacc[2*np],   pf, vf4[0], vf4[1]);
            mma16816h(oacc[2*np+1], pf, vf4[2], vf4[3]);
        }
    }
}

__global__ void __launch_bounds__(256) attn_mma(float* __restrict__ out)
{
    extern __shared__ char smc[];   // 2 halves x 4 stages x 24KB = 192KB
    const uint32_t sb = smem_u32(smc);

    const int tid = threadIdx.x, lane = tid & 31, w = tid >> 5;
    const int t4 = lane & 3, g = lane >> 2;
    const int l8 = lane & 7, sel = lane >> 3;
    const int half = w >> 2, t128 = tid & 127;
    const int bh = blockIdx.y, q0 = blockIdx.x * 128;
    const int r0 = q0 + w * 16 + g;          // rows r0, r0+8
    const uint32_t hb = sb + (uint32_t)half * HALF_SZ;
    const int barid = half + 1;
    const uint4* __restrict__ kvb = g_kv + (size_t)bh * 64 * 1536;

    issue_kv32(hb,               kvb,            t128); CP_COMMIT();
    issue_kv32(hb + STG_SZ,      kvb + 1536,     t128); CP_COMMIT();
    issue_kv32(hb + 2u * STG_SZ, kvb + 2 * 1536, t128); CP_COMMIT();
    issue_kv32(hb + 3u * STG_SZ, kvb + 3 * 1536, t128); CP_COMMIT();

    // Q fragments: frag-linear coalesced LDG.128
    uint32_t qh[8][4], qm[8][4];
    {
        const int rowblk = (bh * Sn + q0 + w * 16) >> 4;
        const uint4* ph4 = g_qfh + (size_t)rowblk * 256 + lane;
        const uint4* pm4 = g_qfm + (size_t)rowblk * 256 + lane;
        #pragma unroll
        for (int j = 0; j < 8; j++) {
            uint4 H = ph4[j * 32];
            uint4 M = pm4[j * 32];
            qh[j][0] = H.x; qh[j][1] = H.y; qh[j][2] = H.z; qh[j][3] = H.w;
            qm[j][0] = M.x; qm[j][1] = M.y; qm[j][2] = M.z; qm[j][3] = M.w;
        }
    }

    float oacc[16][4];
    #pragma unroll
    for (int t = 0; t < 16; t++)
        #pragma unroll
        for (int i = 0; i < 4; i++) oacc[t][i] = 0.f;
    float l0 = 0.f, l1 = 0.f;
    float m0r = -CUDART_INF_F, m1r = -CUDART_INF_F;
    float sA[4][4], sB[4][4];

    // prologue: QK(0) — WAIT2 guarantees tiles 0 and 1 resident
    CP_WAIT2();
    NBAR(barid);
    qk_plain(sA, hb, qh, qm, sel, l8);

#define SUBTILE(kt, CUR, NXT) do {                                            \
    CP_WAIT2();  /* ledger: guarantees groups for tiles kt and kt+1 */        \
    NBAR(barid);                                                              \
    if ((kt) >= 1 && (kt) + 3 < 64)                                           \
        issue_kv32(hb + (uint32_t)(((kt) + 3) & 3) * STG_SZ,                  \
                   kvb + ((kt) + 3) * 1536, t128);                            \
    CP_COMMIT();                                                              \
    uint32_t kb_c = hb + (uint32_t)((kt) & 3) * STG_SZ;                       \
    uint32_t kb_n = hb + (uint32_t)(((kt) + 1) & 3) * STG_SZ;                 \
    float mx0 = -CUDART_INF_F, mx1 = -CUDART_INF_F;                           \
    _Pragma("unroll")                                                         \
    for (int t = 0; t < 4; t++) {                                             \
        mx0 = fmaxf(mx0, fmaxf(CUR[t][0], CUR[t][1]));                        \
        mx1 = fmaxf(mx1, fmaxf(CUR[t][2], CUR[t][3]));                        \
    }                                                                         \
    mx0 = fmaxf(mx0, __shfl_xor_sync(0xffffffffu, mx0, 1));                   \
    mx0 = fmaxf(mx0, __shfl_xor_sync(0xffffffffu, mx0, 2));                   \
    mx1 = fmaxf(mx1, __shfl_xor_sync(0xffffffffu, mx1, 1));                   \
    mx1 = fmaxf(mx1, __shfl_xor_sync(0xffffffffu, mx1, 2));                   \
    float mn0 = fmaxf(m0r, mx0), mn1 = fmaxf(m1r, mx1);                       \
    float sc0 = __expf(m0r - mn0), sc1 = __expf(m1r - mn1);                   \
    m0r = mn0; m1r = mn1;                                                     \
    l0 *= sc0; l1 *= sc1;                                                     \
    if (__any_sync(0xffffffffu, (sc0 < 0.99999f) | (sc1 < 0.99999f))) {       \
        _Pragma("unroll")                                                     \
        for (int t = 0; t < 16; t++) {                                        \
            oacc[t][0] *= sc0; oacc[t][1] *= sc0;                             \
            oacc[t][2] *= sc1; oacc[t][3] *= sc1;                             \
        }                                                                     \
    }                                                                         \
    if ((kt) < 63) qknext_exp(CUR, NXT, kb_n, qh, qm, mn0, mn1, l0, l1, sel, l8); \
    else           exp_only(CUR, mn0, mn1, l0, l1);                           \
    pv_tile(CUR, oacc, kb_c, sel, l8);                                        \
} while (0)

    for (int it = 0; it < 32; it++) {
        int kt = 2 * it;
        SUBTILE(kt,     sA, sB);
        SUBTILE(kt + 1, sB, sA);
    }
#undef SUBTILE

    // ---- epilogue ----
    l0 += __shfl_xor_sync(0xffffffffu, l0, 1);
    l0 += __shfl_xor_sync(0xffffffffu, l0, 2);
    l1 += __shfl_xor_sync(0xffffffffu, l1, 1);
    l1 += __shfl_xor_sync(0xffffffffu, l1, 2);
    const float inv0 = 1.f / l0, inv1 = 1.f / l1;

    const int b = bh >> 4, h = bh & 15;
    const size_t ob0 = (((size_t)b * Sn + r0) * Hn + h) * Dn;
    const size_t ob1 = (((size_t)b * Sn + r0 + 8) * Hn + h) * Dn;
    #pragma unroll
    for (int t = 0; t < 16; t++) {
        int d = t * 8 + 2 * t4;
        *(float2*)(out + ob0 + d) = make_float2(oacc[t][0] * inv0, oacc[t][1] * inv0);
        *(float2*)(out + ob1 + d) = make_float2(oacc[t][2] * inv1, oacc[t][3] * inv1);
    }
}

// ---------------------------------------------------------------------------
extern "C" void kernel_launch(void* const* d_in, const int* in_sizes, int n_in,
                              void* d_out, int out_size)
{
    const float* x  = (const float*)d_in[0];
    const float* Wq = (const float*)d_in[1];
    const float* bq = (const float*)d_in[2];
    const float* Wk = (const float*)d_in[3];
    const float* bk = (const float*)d_in[4];
    const float* Wv = (const float*)d_in[5];
    const float* bv = (const float*)d_in[6];

    const int smem_proj = 65536 + 64 * 132 * 4;    // 99328 -> 2 CTAs/SM
    const int smem_attn = 2 * (int)HALF_SZ;        // 196608

    cudaFuncSetAttribute(proj_mma, cudaFuncAttributeMaxDynamicSharedMemorySize, smem_proj);
    cudaFuncSetAttribute(attn_mma, cudaFuncAttributeMaxDynamicSharedMemorySize, smem_attn);

    prep_w<<<dim3(3, 16), 128>>>(Wq, Wk, Wv);
    proj_mma<<<Mn / 64, 128, smem_proj>>>(x, bq, bk, bv);
    attn_mma<<<dim3(Sn / 128, Bn * Hn), 256, smem_attn>>>((float*)d_out);
}